// round 1
// baseline (speedup 1.0000x reference)
#include <cuda_runtime.h>
#include <cstdint>

#define N_NODES 50000
#define N_EDGES 800000
#define HID 128
#define NUM_GRAPHS 500
#define N_LAYERS 3
#define LN_EPS 1e-5f

// ---------------- scratch (device globals; no allocations allowed) ----------
__device__ float g_deg[N_NODES];                      // degree, then dinv in-place
__device__ float g_h[(size_t)N_NODES * HID];          // node features
__device__ float g_hw[(size_t)N_NODES * HID];         // h @ Wc^T
__device__ float g_agg[(size_t)N_NODES * HID];        // aggregated messages
__device__ float g_pooled[NUM_GRAPHS * HID];
__device__ float g_cnt[NUM_GRAPHS];

// ---------------- init: zero deg / pooled / counts --------------------------
__global__ void k_init() {
    int i = blockIdx.x * blockDim.x + threadIdx.x;
    if (i < N_NODES) g_deg[i] = 0.f;
    if (i < NUM_GRAPHS * HID) g_pooled[i] = 0.f;
    if (i < NUM_GRAPHS) g_cnt[i] = 0.f;
}

// ---------------- degree accumulation ---------------------------------------
__global__ void k_deg(const int* __restrict__ dst) {
    int i = blockIdx.x * blockDim.x + threadIdx.x;
    if (i < N_EDGES) atomicAdd(&g_deg[dst[i]], 1.f);
}

__global__ void k_dinv() {
    int i = blockIdx.x * blockDim.x + threadIdx.x;
    if (i < N_NODES) g_deg[i] = rsqrtf(g_deg[i] + 1.f);
}

// ---------------- GEMM: C[M,128] = A[M,128] @ W[128,128]^T (+bias) ----------
// mode 0: A = A_ext (x), C = g_h, bias added, no C2
// mode 1: A = g_h,  C = g_hw, C2 = g_agg = hw * dinv^2 + bc (self-loop fused)
#define KC 32
#define WSTR 132   // padded k-major W stride (4-float pad: conflict-light stores,
                   // conflict-free 128-bit reads)

__global__ __launch_bounds__(256) void k_gemm(
    const float* A_ext, const float* __restrict__ W,
    const float* __restrict__ bias, const float* __restrict__ bc,
    int M, int mode)
{
    __shared__ float Ws[KC * WSTR];   // 16896 B
    __shared__ float As[64 * KC];     //  8192 B

    const float* A = (mode == 0) ? A_ext : g_h;
    float* C  = (mode == 0) ? g_h  : g_hw;
    float* C2 = (mode == 0) ? (float*)0 : g_agg;

    int t  = threadIdx.x;
    int tx = t & 31;        // col quad: cols tx*4 .. tx*4+3
    int ty = t >> 5;        // row group: rows ty*8 .. ty*8+7
    int row0 = blockIdx.x * 64;

    unsigned long long acc[8][2];
#pragma unroll
    for (int i = 0; i < 8; i++) { acc[i][0] = 0ull; acc[i][1] = 0ull; }

    for (int kc = 0; kc < 128; kc += KC) {
        // W chunk, transposed to k-major: Ws[k][n] = W[n][kc+k]
        for (int i = t; i < KC * 128; i += 256) {
            int n = i >> 5;
            int k = i & 31;
            Ws[k * WSTR + n] = W[n * 128 + kc + k];
        }
        // A chunk (coalesced float4)
        for (int i = t; i < 64 * (KC / 4); i += 256) {
            int r  = i >> 3;
            int kq = i & 7;
            int gr = row0 + r;
            float4 v = make_float4(0.f, 0.f, 0.f, 0.f);
            if (gr < M)
                v = reinterpret_cast<const float4*>(A + (size_t)gr * 128 + kc)[kq];
            reinterpret_cast<float4*>(As + r * KC)[kq] = v;
        }
        __syncthreads();

        int c0 = tx * 4;
        int r0 = ty * 8;
#pragma unroll
        for (int k = 0; k < KC; ++k) {
            float4 w = *reinterpret_cast<const float4*>(&Ws[k * WSTR + c0]);
            unsigned long long w01, w23;
            asm("mov.b64 %0, {%1,%2};" : "=l"(w01) : "f"(w.x), "f"(w.y));
            asm("mov.b64 %0, {%1,%2};" : "=l"(w23) : "f"(w.z), "f"(w.w));
#pragma unroll
            for (int i = 0; i < 8; ++i) {
                float a = As[(r0 + i) * KC + k];     // warp-broadcast LDS
                unsigned long long aa;
                asm("mov.b64 %0, {%1,%1};" : "=l"(aa) : "f"(a));
                asm("fma.rn.f32x2 %0, %1, %2, %0;" : "+l"(acc[i][0]) : "l"(aa), "l"(w01));
                asm("fma.rn.f32x2 %0, %1, %2, %0;" : "+l"(acc[i][1]) : "l"(aa), "l"(w23));
            }
        }
        __syncthreads();
    }

    // epilogue
    int c0 = tx * 4;
    int r0 = ty * 8;
    float4 bv  = make_float4(0.f, 0.f, 0.f, 0.f);
    if (bias) bv  = *reinterpret_cast<const float4*>(bias + c0);
    float4 bcv = make_float4(0.f, 0.f, 0.f, 0.f);
    if (C2)   bcv = *reinterpret_cast<const float4*>(bc + c0);

#pragma unroll
    for (int i = 0; i < 8; ++i) {
        int gr = row0 + r0 + i;
        if (gr >= M) break;
        float4 v;
        asm("mov.b64 {%0,%1}, %2;" : "=f"(v.x), "=f"(v.y) : "l"(acc[i][0]));
        asm("mov.b64 {%0,%1}, %2;" : "=f"(v.z), "=f"(v.w) : "l"(acc[i][1]));
        v.x += bv.x; v.y += bv.y; v.z += bv.z; v.w += bv.w;
        reinterpret_cast<float4*>(C + (size_t)gr * 128)[tx] = v;
        if (C2) {
            float dv = g_deg[gr];            // holds dinv
            float sn = dv * dv;
            float4 v2 = make_float4(v.x * sn + bcv.x, v.y * sn + bcv.y,
                                    v.z * sn + bcv.z, v.w * sn + bcv.w);
            reinterpret_cast<float4*>(C2 + (size_t)gr * 128)[tx] = v2;
        }
    }
}

// ---------------- edge scatter: agg[dst] += hw[src] * dinv[s]*dinv[d] -------
// One warp per edge; float4 per lane; vector reduction (sm_90+ red.v4.f32).
__global__ __launch_bounds__(256) void k_scatter(const int* __restrict__ src,
                                                 const int* __restrict__ dst) {
    int wg   = (blockIdx.x * blockDim.x + threadIdx.x) >> 5;
    int lane = threadIdx.x & 31;
    if (wg >= N_EDGES) return;
    int s = src[wg];
    int d = dst[wg];
    float w = g_deg[s] * g_deg[d];                  // dinv[s]*dinv[d]
    float4 v = reinterpret_cast<const float4*>(g_hw + (size_t)s * HID)[lane];
    float* p = g_agg + (size_t)d * HID + lane * 4;
    asm volatile("red.global.add.v4.f32 [%0], {%1,%2,%3,%4};"
                 :: "l"(p), "f"(v.x * w), "f"(v.y * w), "f"(v.z * w), "f"(v.w * w)
                 : "memory");
}

// ---------------- fused LayerNorm + ReLU + residual (warp per node) ---------
__global__ __launch_bounds__(256) void k_ln(const float* __restrict__ gamma,
                                            const float* __restrict__ beta) {
    int node = (blockIdx.x * blockDim.x + threadIdx.x) >> 5;
    int lane = threadIdx.x & 31;
    if (node >= N_NODES) return;
    float4 v = reinterpret_cast<const float4*>(g_agg + (size_t)node * HID)[lane];
    float s = v.x + v.y + v.z + v.w;
#pragma unroll
    for (int o = 16; o > 0; o >>= 1) s += __shfl_xor_sync(0xffffffffu, s, o);
    float mu = s * (1.f / 128.f);
    float dx = v.x - mu, dy = v.y - mu, dz = v.z - mu, dw = v.w - mu;
    float q = dx * dx + dy * dy + dz * dz + dw * dw;
#pragma unroll
    for (int o = 16; o > 0; o >>= 1) q += __shfl_xor_sync(0xffffffffu, q, o);
    float rs = rsqrtf(q * (1.f / 128.f) + LN_EPS);
    float4 gm = reinterpret_cast<const float4*>(gamma)[lane];
    float4 bt = reinterpret_cast<const float4*>(beta)[lane];
    float4 r  = reinterpret_cast<const float4*>(g_h + (size_t)node * HID)[lane];
    float4 o;
    o.x = fmaxf(dx * rs * gm.x + bt.x, 0.f) + r.x;
    o.y = fmaxf(dy * rs * gm.y + bt.y, 0.f) + r.y;
    o.z = fmaxf(dz * rs * gm.z + bt.z, 0.f) + r.z;
    o.w = fmaxf(dw * rs * gm.w + bt.w, 0.f) + r.w;
    reinterpret_cast<float4*>(g_h + (size_t)node * HID)[lane] = o;
}

// ---------------- sorted-batch segmented pooling ----------------------------
#define POOL_RPB 512
__global__ __launch_bounds__(128) void k_pool(const int* __restrict__ batch) {
    int t  = threadIdx.x;                      // = feature column
    int r0 = blockIdx.x * POOL_RPB;
    int r1 = min(r0 + POOL_RPB, N_NODES);
    if (r0 >= N_NODES) return;
    float acc = 0.f, cacc = 0.f;
    int gcur = batch[r0];
    for (int r = r0; r < r1; ++r) {
        int g = batch[r];                      // broadcast load
        if (g != gcur) {
            atomicAdd(&g_pooled[gcur * HID + t], acc);
            if (t == 0) atomicAdd(&g_cnt[gcur], cacc);
            acc = 0.f; cacc = 0.f; gcur = g;
        }
        acc  += g_h[(size_t)r * HID + t];
        cacc += 1.f;
    }
    atomicAdd(&g_pooled[gcur * HID + t], acc);
    if (t == 0) atomicAdd(&g_cnt[gcur], cacc);
}

// ---------------- final MLP: out = relu(pooled@W1^T+b1)@W2^T+b2 -------------
__global__ __launch_bounds__(64) void k_mlp(const float* __restrict__ W1,
                                            const float* __restrict__ b1,
                                            const float* __restrict__ W2,
                                            const float* __restrict__ b2,
                                            float* __restrict__ out) {
    __shared__ float sp[128];
    __shared__ float part[2];
    int g = blockIdx.x, t = threadIdx.x;
    float inv = 1.f / fmaxf(g_cnt[g], 1.f);
    sp[t]      = g_pooled[g * HID + t] * inv;
    sp[t + 64] = g_pooled[g * HID + 64 + t] * inv;
    __syncthreads();
    float a = b1[t];
#pragma unroll 8
    for (int k = 0; k < 128; ++k) a += sp[k] * W1[t * 128 + k];
    a = fmaxf(a, 0.f);
    float v = a * W2[t];
#pragma unroll
    for (int o = 16; o > 0; o >>= 1) v += __shfl_xor_sync(0xffffffffu, v, o);
    if ((t & 31) == 0) part[t >> 5] = v;
    __syncthreads();
    if (t == 0) out[g] = part[0] + part[1] + b2[0];
}

// ---------------- launch ----------------------------------------------------
extern "C" void kernel_launch(void* const* d_in, const int* in_sizes, int n_in,
                              void* d_out, int out_size) {
    const float* x     = (const float*)d_in[0];
    const int*   ei    = (const int*)  d_in[1];
    const int*   batch = (const int*)  d_in[2];
    const float* W_in  = (const float*)d_in[3];
    const float* b_in  = (const float*)d_in[4];
    const float* Wc    = (const float*)d_in[5];
    const float* bc    = (const float*)d_in[6];
    const float* gamma = (const float*)d_in[7];
    const float* beta  = (const float*)d_in[8];
    const float* W1    = (const float*)d_in[9];
    const float* b1    = (const float*)d_in[10];
    const float* W2    = (const float*)d_in[11];
    const float* b2    = (const float*)d_in[12];
    float* out = (float*)d_out;

    const int* src = ei;
    const int* dst = ei + N_EDGES;

    k_init<<<(NUM_GRAPHS * HID + 255) / 256, 256>>>();
    k_deg<<<(N_EDGES + 255) / 256, 256>>>(dst);
    k_dinv<<<(N_NODES + 255) / 256, 256>>>();

    int gemm_blocks = (N_NODES + 63) / 64;
    // input projection: h = x @ W_in^T + b_in
    k_gemm<<<gemm_blocks, 256>>>(x, W_in, b_in, (const float*)0, N_NODES, 0);

    int scat_blocks = (N_EDGES * 32 + 255) / 256;
    int ln_blocks   = (N_NODES * 32 + 255) / 256;
    for (int l = 0; l < N_LAYERS; ++l) {
        // hw = h @ Wc[l]^T ; agg = hw*dinv^2 + bc[l] (fused epilogue)
        k_gemm<<<gemm_blocks, 256>>>((const float*)0, Wc + (size_t)l * HID * HID,
                                     (const float*)0, bc + l * HID, N_NODES, 1);
        k_scatter<<<scat_blocks, 256>>>(src, dst);
        k_ln<<<ln_blocks, 256>>>(gamma + l * HID, beta + l * HID);
    }

    k_pool<<<(N_NODES + POOL_RPB - 1) / POOL_RPB, 128>>>(batch);
    k_mlp<<<NUM_GRAPHS, 64>>>(W1, b1, W2, b2, out);
}

// round 2
// speedup vs baseline: 1.4656x; 1.4656x over previous
#include <cuda_runtime.h>
#include <cstdint>

#define N_NODES 50000
#define N_EDGES 800000
#define HID 128
#define NUM_GRAPHS 500
#define N_LAYERS 3
#define LN_EPS 1e-5f

// ---------------- scratch (device globals) ----------------------------------
__device__ float g_deg[N_NODES];                      // dinv
__device__ int   g_indeg[N_NODES];
__device__ int   g_off[N_NODES + 1];
__device__ int   g_cur[N_NODES];
__device__ int   g_esrc[N_EDGES];
__device__ float g_ew[N_EDGES];
__device__ float g_h[(size_t)N_NODES * HID];
__device__ float g_hw[(size_t)N_NODES * HID];
__device__ float g_pooled[NUM_GRAPHS * HID];
__device__ float g_cnt[NUM_GRAPHS];

// ---------------- init -------------------------------------------------------
__global__ void k_init() {
    int i = blockIdx.x * blockDim.x + threadIdx.x;
    if (i < N_NODES) g_indeg[i] = 0;
    if (i < NUM_GRAPHS * HID) g_pooled[i] = 0.f;
    if (i < NUM_GRAPHS) g_cnt[i] = 0.f;
}

// ---------------- in-degree histogram ----------------------------------------
__global__ void k_hist(const int* __restrict__ dst) {
    int i = blockIdx.x * blockDim.x + threadIdx.x;
    if (i < N_EDGES) atomicAdd(&g_indeg[dst[i]], 1);
}

// ---------------- single-block scan: offsets + cursors + dinv -----------------
__global__ __launch_bounds__(1024) void k_scan() {
    __shared__ int warp_sums[32];
    __shared__ int s_carry;
    int t = threadIdx.x, lane = t & 31, wid = t >> 5;
    if (t == 0) s_carry = 0;
    __syncthreads();
    for (int base = 0; base < N_NODES; base += 1024) {
        int i = base + t;
        int v = (i < N_NODES) ? g_indeg[i] : 0;
        int x = v;
#pragma unroll
        for (int o = 1; o < 32; o <<= 1) {
            int y = __shfl_up_sync(0xffffffffu, x, o);
            if (lane >= o) x += y;
        }
        if (lane == 31) warp_sums[wid] = x;
        __syncthreads();
        if (wid == 0) {
            int s = warp_sums[lane];
#pragma unroll
            for (int o = 1; o < 32; o <<= 1) {
                int y = __shfl_up_sync(0xffffffffu, s, o);
                if (lane >= o) s += y;
            }
            warp_sums[lane] = s;
        }
        __syncthreads();
        int off = s_carry + (wid ? warp_sums[wid - 1] : 0) + (x - v);
        if (i < N_NODES) {
            g_off[i] = off;
            g_cur[i] = off;
            g_deg[i] = rsqrtf((float)v + 1.f);
        }
        __syncthreads();
        if (t == 0) s_carry += warp_sums[31];
        __syncthreads();
    }
    if (t == 0) g_off[N_NODES] = s_carry;
}

// ---------------- CSR bucket fill --------------------------------------------
__global__ void k_fill(const int* __restrict__ src, const int* __restrict__ dst) {
    int e = blockIdx.x * blockDim.x + threadIdx.x;
    if (e >= N_EDGES) return;
    int s = src[e], d = dst[e];
    int slot = atomicAdd(&g_cur[d], 1);
    g_esrc[slot] = s;
    g_ew[slot] = g_deg[s] * g_deg[d];
}

// ---------------- GEMM: C[M,128] = A[M,128] @ W[128,128]^T (+bias) -----------
// mode 0: A = A_ext (x), C = g_h    mode 1: A = g_h, C = g_hw
#define KC 32
#define WSTR 132

__global__ __launch_bounds__(256, 3) void k_gemm(
    const float* A_ext, const float* __restrict__ W,
    const float* __restrict__ bias, int M, int mode)
{
    __shared__ float Ws[KC * WSTR];        // 16896 B
    __shared__ float As2[64 * KC * 2];     // 16384 B (duplicated pairs)

    const float* A = (mode == 0) ? A_ext : g_h;
    float* C = (mode == 0) ? g_h : g_hw;

    int t  = threadIdx.x;
    int tx = t & 31;        // col quad: cols tx*4 .. tx*4+3
    int ty = t >> 5;        // row group: rows ty*8 .. ty*8+7
    int row0 = blockIdx.x * 64;

    unsigned long long acc[8][2];
#pragma unroll
    for (int i = 0; i < 8; i++) { acc[i][0] = 0ull; acc[i][1] = 0ull; }

    for (int kc = 0; kc < 128; kc += KC) {
        // W chunk transposed to k-major: Ws[k][n] = W[n][kc+k]
        for (int i = t; i < KC * 128; i += 256) {
            int n = i >> 5;
            int k = i & 31;
            Ws[k * WSTR + n] = W[n * 128 + kc + k];
        }
        // A chunk, stored duplicated: As2[r*64 + 2k + {0,1}] = a(r,k)
        for (int i = t; i < 64 * (KC / 4); i += 256) {
            int r  = i >> 3;
            int kq = i & 7;
            int gr = row0 + r;
            float4 v = make_float4(0.f, 0.f, 0.f, 0.f);
            if (gr < M)
                v = reinterpret_cast<const float4*>(A + (size_t)gr * 128 + kc)[kq];
            float* p = As2 + r * (KC * 2) + kq * 8;
            reinterpret_cast<float4*>(p)[0] = make_float4(v.x, v.x, v.y, v.y);
            reinterpret_cast<float4*>(p)[1] = make_float4(v.z, v.z, v.w, v.w);
        }
        __syncthreads();

        int c0 = tx * 4;
        const float* asrow = As2 + (ty * 8) * (KC * 2);
#pragma unroll
        for (int k = 0; k < KC; k += 2) {
            ulonglong2 w0 = *reinterpret_cast<const ulonglong2*>(&Ws[k * WSTR + c0]);
            ulonglong2 w1 = *reinterpret_cast<const ulonglong2*>(&Ws[(k + 1) * WSTR + c0]);
#pragma unroll
            for (int i = 0; i < 8; ++i) {
                ulonglong2 aa = *reinterpret_cast<const ulonglong2*>(
                    asrow + i * (KC * 2) + k * 2);     // {a_k,a_k,a_k1,a_k1} broadcast
                asm("fma.rn.f32x2 %0, %1, %2, %0;" : "+l"(acc[i][0]) : "l"(aa.x), "l"(w0.x));
                asm("fma.rn.f32x2 %0, %1, %2, %0;" : "+l"(acc[i][1]) : "l"(aa.x), "l"(w0.y));
                asm("fma.rn.f32x2 %0, %1, %2, %0;" : "+l"(acc[i][0]) : "l"(aa.y), "l"(w1.x));
                asm("fma.rn.f32x2 %0, %1, %2, %0;" : "+l"(acc[i][1]) : "l"(aa.y), "l"(w1.y));
            }
        }
        __syncthreads();
    }

    int c0 = tx * 4;
    int r0 = ty * 8;
    float4 bv = make_float4(0.f, 0.f, 0.f, 0.f);
    if (bias) bv = *reinterpret_cast<const float4*>(bias + c0);

#pragma unroll
    for (int i = 0; i < 8; ++i) {
        int gr = row0 + r0 + i;
        if (gr >= M) break;
        float4 v;
        asm("mov.b64 {%0,%1}, %2;" : "=f"(v.x), "=f"(v.y) : "l"(acc[i][0]));
        asm("mov.b64 {%0,%1}, %2;" : "=f"(v.z), "=f"(v.w) : "l"(acc[i][1]));
        v.x += bv.x; v.y += bv.y; v.z += bv.z; v.w += bv.w;
        reinterpret_cast<float4*>(C + (size_t)gr * 128)[tx] = v;
    }
}

// ---------------- fused gather + self-loop + LN + ReLU + residual ------------
// warp per dst node: acc = hw[d]*dinv[d]^2 + bc + sum_e w_e * hw[src_e]
// then LayerNorm, ReLU, + residual(g_h), write g_h.
__global__ __launch_bounds__(256) void k_gatherln(
    const float* __restrict__ bc,
    const float* __restrict__ gamma, const float* __restrict__ beta)
{
    int node = (blockIdx.x * blockDim.x + threadIdx.x) >> 5;
    int lane = threadIdx.x & 31;
    if (node >= N_NODES) return;

    int e0 = g_off[node], e1 = g_off[node + 1];
    float dv = g_deg[node];
    float sn = dv * dv;

    float4 hv  = reinterpret_cast<const float4*>(g_hw + (size_t)node * HID)[lane];
    float4 bcv = reinterpret_cast<const float4*>(bc)[lane];
    float4 acc = make_float4(hv.x * sn + bcv.x, hv.y * sn + bcv.y,
                             hv.z * sn + bcv.z, hv.w * sn + bcv.w);

    int e = e0;
    for (; e + 1 < e1; e += 2) {
        int s0 = g_esrc[e];
        int s1 = g_esrc[e + 1];
        float w0 = g_ew[e];
        float w1 = g_ew[e + 1];
        float4 v0 = reinterpret_cast<const float4*>(g_hw + (size_t)s0 * HID)[lane];
        float4 v1 = reinterpret_cast<const float4*>(g_hw + (size_t)s1 * HID)[lane];
        acc.x += w0 * v0.x + w1 * v1.x;
        acc.y += w0 * v0.y + w1 * v1.y;
        acc.z += w0 * v0.z + w1 * v1.z;
        acc.w += w0 * v0.w + w1 * v1.w;
    }
    if (e < e1) {
        int s0 = g_esrc[e];
        float w0 = g_ew[e];
        float4 v0 = reinterpret_cast<const float4*>(g_hw + (size_t)s0 * HID)[lane];
        acc.x += w0 * v0.x; acc.y += w0 * v0.y;
        acc.z += w0 * v0.z; acc.w += w0 * v0.w;
    }

    // LayerNorm over 128 features
    float s = acc.x + acc.y + acc.z + acc.w;
#pragma unroll
    for (int o = 16; o > 0; o >>= 1) s += __shfl_xor_sync(0xffffffffu, s, o);
    float mu = s * (1.f / 128.f);
    float dx = acc.x - mu, dy = acc.y - mu, dz = acc.z - mu, dw = acc.w - mu;
    float q = dx * dx + dy * dy + dz * dz + dw * dw;
#pragma unroll
    for (int o = 16; o > 0; o >>= 1) q += __shfl_xor_sync(0xffffffffu, q, o);
    float rs = rsqrtf(q * (1.f / 128.f) + LN_EPS);

    float4 gm = reinterpret_cast<const float4*>(gamma)[lane];
    float4 bt = reinterpret_cast<const float4*>(beta)[lane];
    float4 r  = reinterpret_cast<const float4*>(g_h + (size_t)node * HID)[lane];
    float4 o;
    o.x = fmaxf(dx * rs * gm.x + bt.x, 0.f) + r.x;
    o.y = fmaxf(dy * rs * gm.y + bt.y, 0.f) + r.y;
    o.z = fmaxf(dz * rs * gm.z + bt.z, 0.f) + r.z;
    o.w = fmaxf(dw * rs * gm.w + bt.w, 0.f) + r.w;
    reinterpret_cast<float4*>(g_h + (size_t)node * HID)[lane] = o;
}

// ---------------- sorted-batch segmented pooling -----------------------------
#define POOL_RPB 128
__global__ __launch_bounds__(128) void k_pool(const int* __restrict__ batch) {
    int t  = threadIdx.x;                      // feature column
    int r0 = blockIdx.x * POOL_RPB;
    int r1 = min(r0 + POOL_RPB, N_NODES);
    if (r0 >= N_NODES) return;
    float acc = 0.f, cacc = 0.f;
    int gcur = batch[r0];
    for (int r = r0; r < r1; ++r) {
        int g = batch[r];
        if (g != gcur) {
            atomicAdd(&g_pooled[gcur * HID + t], acc);
            if (t == 0) atomicAdd(&g_cnt[gcur], cacc);
            acc = 0.f; cacc = 0.f; gcur = g;
        }
        acc  += g_h[(size_t)r * HID + t];
        cacc += 1.f;
    }
    atomicAdd(&g_pooled[gcur * HID + t], acc);
    if (t == 0) atomicAdd(&g_cnt[gcur], cacc);
}

// ---------------- final MLP --------------------------------------------------
__global__ __launch_bounds__(64) void k_mlp(const float* __restrict__ W1,
                                            const float* __restrict__ b1,
                                            const float* __restrict__ W2,
                                            const float* __restrict__ b2,
                                            float* __restrict__ out) {
    __shared__ float sp[128];
    __shared__ float part[2];
    int g = blockIdx.x, t = threadIdx.x;
    float inv = 1.f / fmaxf(g_cnt[g], 1.f);
    sp[t]      = g_pooled[g * HID + t] * inv;
    sp[t + 64] = g_pooled[g * HID + 64 + t] * inv;
    __syncthreads();
    float a = b1[t];
#pragma unroll 8
    for (int k = 0; k < 128; ++k) a += sp[k] * W1[t * 128 + k];
    a = fmaxf(a, 0.f);
    float v = a * W2[t];
#pragma unroll
    for (int o = 16; o > 0; o >>= 1) v += __shfl_xor_sync(0xffffffffu, v, o);
    if ((t & 31) == 0) part[t >> 5] = v;
    __syncthreads();
    if (t == 0) out[g] = part[0] + part[1] + b2[0];
}

// ---------------- launch -----------------------------------------------------
extern "C" void kernel_launch(void* const* d_in, const int* in_sizes, int n_in,
                              void* d_out, int out_size) {
    const float* x     = (const float*)d_in[0];
    const int*   ei    = (const int*)  d_in[1];
    const int*   batch = (const int*)  d_in[2];
    const float* W_in  = (const float*)d_in[3];
    const float* b_in  = (const float*)d_in[4];
    const float* Wc    = (const float*)d_in[5];
    const float* bc    = (const float*)d_in[6];
    const float* gamma = (const float*)d_in[7];
    const float* beta  = (const float*)d_in[8];
    const float* W1    = (const float*)d_in[9];
    const float* b1    = (const float*)d_in[10];
    const float* W2    = (const float*)d_in[11];
    const float* b2    = (const float*)d_in[12];
    float* out = (float*)d_out;

    const int* src = ei;
    const int* dst = ei + N_EDGES;

    k_init<<<(NUM_GRAPHS * HID + 255) / 256, 256>>>();
    k_hist<<<(N_EDGES + 255) / 256, 256>>>(dst);
    k_scan<<<1, 1024>>>();
    k_fill<<<(N_EDGES + 255) / 256, 256>>>(src, dst);

    int gemm_blocks = (N_NODES + 63) / 64;
    k_gemm<<<gemm_blocks, 256>>>(x, W_in, b_in, N_NODES, 0);

    int gl_blocks = (N_NODES * 32 + 255) / 256;
    for (int l = 0; l < N_LAYERS; ++l) {
        k_gemm<<<gemm_blocks, 256>>>((const float*)0, Wc + (size_t)l * HID * HID,
                                     (const float*)0, N_NODES, 1);
        k_gatherln<<<gl_blocks, 256>>>(bc + l * HID, gamma + l * HID, beta + l * HID);
    }

    k_pool<<<(N_NODES + POOL_RPB - 1) / POOL_RPB, 128>>>(batch);
    k_mlp<<<NUM_GRAPHS, 64>>>(W1, b1, W2, b2, out);
}

// round 3
// speedup vs baseline: 1.5708x; 1.0717x over previous
#include <cuda_runtime.h>
#include <cstdint>

#define N_NODES 50000
#define N_EDGES 800000
#define HID 128
#define NUM_GRAPHS 500
#define N_LAYERS 3
#define LN_EPS 1e-5f

// ---------------- scratch (device globals) ----------------------------------
__device__ float g_deg[N_NODES];                      // dinv
__device__ int   g_indeg[N_NODES];
__device__ int   g_off[N_NODES + 1];
__device__ int   g_cur[N_NODES];
__device__ int   g_esrc[N_EDGES];
__device__ float g_ew[N_EDGES];
__device__ float g_h[(size_t)N_NODES * HID];
__device__ float g_hw[(size_t)N_NODES * HID];
__device__ float g_pooled[NUM_GRAPHS * HID];
__device__ float g_cnt[NUM_GRAPHS];

// ---------------- init -------------------------------------------------------
__global__ void k_init() {
    int i = blockIdx.x * blockDim.x + threadIdx.x;
    if (i < N_NODES) g_indeg[i] = 0;
    if (i < NUM_GRAPHS * HID) g_pooled[i] = 0.f;
    if (i < NUM_GRAPHS) g_cnt[i] = 0.f;
}

// ---------------- in-degree histogram ----------------------------------------
__global__ void k_hist(const int* __restrict__ dst) {
    int i = blockIdx.x * blockDim.x + threadIdx.x;
    if (i < N_EDGES) atomicAdd(&g_indeg[dst[i]], 1);
}

// ---------------- single-block scan: offsets + cursors + dinv -----------------
__global__ __launch_bounds__(1024) void k_scan() {
    __shared__ int warp_sums[32];
    __shared__ int s_carry;
    int t = threadIdx.x, lane = t & 31, wid = t >> 5;
    if (t == 0) s_carry = 0;
    __syncthreads();
    for (int base = 0; base < N_NODES; base += 1024) {
        int i = base + t;
        int v = (i < N_NODES) ? g_indeg[i] : 0;
        int x = v;
#pragma unroll
        for (int o = 1; o < 32; o <<= 1) {
            int y = __shfl_up_sync(0xffffffffu, x, o);
            if (lane >= o) x += y;
        }
        if (lane == 31) warp_sums[wid] = x;
        __syncthreads();
        if (wid == 0) {
            int s = warp_sums[lane];
#pragma unroll
            for (int o = 1; o < 32; o <<= 1) {
                int y = __shfl_up_sync(0xffffffffu, s, o);
                if (lane >= o) s += y;
            }
            warp_sums[lane] = s;
        }
        __syncthreads();
        int off = s_carry + (wid ? warp_sums[wid - 1] : 0) + (x - v);
        if (i < N_NODES) {
            g_off[i] = off;
            g_cur[i] = off;
            g_deg[i] = rsqrtf((float)v + 1.f);
        }
        __syncthreads();
        if (t == 0) s_carry += warp_sums[31];
        __syncthreads();
    }
    if (t == 0) g_off[N_NODES] = s_carry;
}

// ---------------- CSR bucket fill --------------------------------------------
__global__ void k_fill(const int* __restrict__ src, const int* __restrict__ dst) {
    int e = blockIdx.x * blockDim.x + threadIdx.x;
    if (e >= N_EDGES) return;
    int s = src[e], d = dst[e];
    int slot = atomicAdd(&g_cur[d], 1);
    g_esrc[slot] = s;
    g_ew[slot] = g_deg[s] * g_deg[d];
}

// ---------------- GEMM: C[M,128] = A[M,128] @ W[128,128]^T (+bias) -----------
// 128x128 block, 256 threads, 8 rows x 8 cols per thread (f32x2 accumulators).
// mode 0: A = A_ext (x), C = g_h    mode 1: A = g_h, C = g_hw
#define KC 16
#define WSTR 132   // Ws row stride (floats), 16B-aligned rows, conflict-light
#define ASTR 36    // As2 row stride (floats), 16B-aligned, conflict-light

__global__ __launch_bounds__(256, 2) void k_gemm(
    const float* A_ext, const float* __restrict__ W,
    const float* __restrict__ bias, int M, int mode)
{
    __shared__ float Ws[KC * WSTR];         // 8448 B, k-major W
    __shared__ float As2[128 * ASTR];       // 18432 B, duplicated A pairs

    const float* A = (mode == 0) ? A_ext : g_h;
    float* C = (mode == 0) ? g_h : g_hw;

    int t  = threadIdx.x;
    int tx = t & 15;        // col groups: c0a = tx*4, c0b = 64 + tx*4
    int ty = t >> 4;        // rows ty*8 .. ty*8+7
    int row0 = blockIdx.x * 128;
    int c0a = tx * 4;
    int c0b = 64 + tx * 4;
    int r0 = ty * 8;

    unsigned long long acc[8][4];
#pragma unroll
    for (int i = 0; i < 8; i++) {
        acc[i][0] = 0ull; acc[i][1] = 0ull; acc[i][2] = 0ull; acc[i][3] = 0ull;
    }

    for (int kc = 0; kc < 128; kc += KC) {
        // W chunk transposed to k-major: Ws[k][n] = W[n][kc+k]
        // thread i: n = i>>4, k = i&15 -> coalesced 64B global reads per n
        for (int i = t; i < KC * 128; i += 256) {
            int n = i >> 4;
            int k = i & 15;
            Ws[k * WSTR + n] = W[n * 128 + kc + k];
        }
        // A chunk, duplicated pairs: As2[r][2k+{0,1}] = a(r, kc+k)
        // thread i: r = i>>2, kq = i&3 (float4 of 4 k's)
        for (int i = t; i < 128 * (KC / 4); i += 256) {
            int r  = i >> 2;
            int kq = i & 3;
            int gr = row0 + r;
            float4 v = make_float4(0.f, 0.f, 0.f, 0.f);
            if (gr < M)
                v = reinterpret_cast<const float4*>(A + (size_t)gr * 128 + kc)[kq];
            float* p = As2 + r * ASTR + kq * 8;
            reinterpret_cast<float4*>(p)[0] = make_float4(v.x, v.x, v.y, v.y);
            reinterpret_cast<float4*>(p)[1] = make_float4(v.z, v.z, v.w, v.w);
        }
        __syncthreads();

#pragma unroll
        for (int k = 0; k < KC; k += 2) {
            ulonglong2 wa0 = *reinterpret_cast<const ulonglong2*>(&Ws[k * WSTR + c0a]);
            ulonglong2 wb0 = *reinterpret_cast<const ulonglong2*>(&Ws[k * WSTR + c0b]);
            ulonglong2 wa1 = *reinterpret_cast<const ulonglong2*>(&Ws[(k + 1) * WSTR + c0a]);
            ulonglong2 wb1 = *reinterpret_cast<const ulonglong2*>(&Ws[(k + 1) * WSTR + c0b]);
#pragma unroll
            for (int i = 0; i < 8; ++i) {
                ulonglong2 aa = *reinterpret_cast<const ulonglong2*>(
                    As2 + (r0 + i) * ASTR + k * 2);   // {ak,ak},{ak1,ak1} broadcast
                asm("fma.rn.f32x2 %0, %1, %2, %0;" : "+l"(acc[i][0]) : "l"(aa.x), "l"(wa0.x));
                asm("fma.rn.f32x2 %0, %1, %2, %0;" : "+l"(acc[i][1]) : "l"(aa.x), "l"(wa0.y));
                asm("fma.rn.f32x2 %0, %1, %2, %0;" : "+l"(acc[i][2]) : "l"(aa.x), "l"(wb0.x));
                asm("fma.rn.f32x2 %0, %1, %2, %0;" : "+l"(acc[i][3]) : "l"(aa.x), "l"(wb0.y));
                asm("fma.rn.f32x2 %0, %1, %2, %0;" : "+l"(acc[i][0]) : "l"(aa.y), "l"(wa1.x));
                asm("fma.rn.f32x2 %0, %1, %2, %0;" : "+l"(acc[i][1]) : "l"(aa.y), "l"(wa1.y));
                asm("fma.rn.f32x2 %0, %1, %2, %0;" : "+l"(acc[i][2]) : "l"(aa.y), "l"(wb1.x));
                asm("fma.rn.f32x2 %0, %1, %2, %0;" : "+l"(acc[i][3]) : "l"(aa.y), "l"(wb1.y));
            }
        }
        __syncthreads();
    }

    float4 bva = make_float4(0.f, 0.f, 0.f, 0.f);
    float4 bvb = make_float4(0.f, 0.f, 0.f, 0.f);
    if (bias) {
        bva = *reinterpret_cast<const float4*>(bias + c0a);
        bvb = *reinterpret_cast<const float4*>(bias + c0b);
    }

#pragma unroll
    for (int i = 0; i < 8; ++i) {
        int gr = row0 + r0 + i;
        if (gr >= M) break;
        float4 va, vb;
        asm("mov.b64 {%0,%1}, %2;" : "=f"(va.x), "=f"(va.y) : "l"(acc[i][0]));
        asm("mov.b64 {%0,%1}, %2;" : "=f"(va.z), "=f"(va.w) : "l"(acc[i][1]));
        asm("mov.b64 {%0,%1}, %2;" : "=f"(vb.x), "=f"(vb.y) : "l"(acc[i][2]));
        asm("mov.b64 {%0,%1}, %2;" : "=f"(vb.z), "=f"(vb.w) : "l"(acc[i][3]));
        va.x += bva.x; va.y += bva.y; va.z += bva.z; va.w += bva.w;
        vb.x += bvb.x; vb.y += bvb.y; vb.z += bvb.z; vb.w += bvb.w;
        float* crow = C + (size_t)gr * 128;
        *reinterpret_cast<float4*>(crow + c0a) = va;
        *reinterpret_cast<float4*>(crow + c0b) = vb;
    }
}

// ---------------- fused gather + self-loop + LN + ReLU + residual ------------
// warp per dst node, edge loop unrolled x4 for memory-level parallelism.
__global__ __launch_bounds__(256) void k_gatherln(
    const float* __restrict__ bc,
    const float* __restrict__ gamma, const float* __restrict__ beta)
{
    int node = (blockIdx.x * blockDim.x + threadIdx.x) >> 5;
    int lane = threadIdx.x & 31;
    if (node >= N_NODES) return;

    int e0 = g_off[node], e1 = g_off[node + 1];
    float dv = g_deg[node];
    float sn = dv * dv;

    float4 hv  = reinterpret_cast<const float4*>(g_hw + (size_t)node * HID)[lane];
    float4 bcv = reinterpret_cast<const float4*>(bc)[lane];
    float4 acc = make_float4(hv.x * sn + bcv.x, hv.y * sn + bcv.y,
                             hv.z * sn + bcv.z, hv.w * sn + bcv.w);

    int e = e0;
#pragma unroll 1
    for (; e + 3 < e1; e += 4) {
        int s0 = g_esrc[e],     s1 = g_esrc[e + 1];
        int s2 = g_esrc[e + 2], s3 = g_esrc[e + 3];
        float w0 = g_ew[e],     w1 = g_ew[e + 1];
        float w2 = g_ew[e + 2], w3 = g_ew[e + 3];
        float4 v0 = reinterpret_cast<const float4*>(g_hw + (size_t)s0 * HID)[lane];
        float4 v1 = reinterpret_cast<const float4*>(g_hw + (size_t)s1 * HID)[lane];
        float4 v2 = reinterpret_cast<const float4*>(g_hw + (size_t)s2 * HID)[lane];
        float4 v3 = reinterpret_cast<const float4*>(g_hw + (size_t)s3 * HID)[lane];
        acc.x += w0 * v0.x + w1 * v1.x + w2 * v2.x + w3 * v3.x;
        acc.y += w0 * v0.y + w1 * v1.y + w2 * v2.y + w3 * v3.y;
        acc.z += w0 * v0.z + w1 * v1.z + w2 * v2.z + w3 * v3.z;
        acc.w += w0 * v0.w + w1 * v1.w + w2 * v2.w + w3 * v3.w;
    }
#pragma unroll 1
    for (; e < e1; ++e) {
        int s0 = g_esrc[e];
        float w0 = g_ew[e];
        float4 v0 = reinterpret_cast<const float4*>(g_hw + (size_t)s0 * HID)[lane];
        acc.x += w0 * v0.x; acc.y += w0 * v0.y;
        acc.z += w0 * v0.z; acc.w += w0 * v0.w;
    }

    // LayerNorm over 128 features
    float s = acc.x + acc.y + acc.z + acc.w;
#pragma unroll
    for (int o = 16; o > 0; o >>= 1) s += __shfl_xor_sync(0xffffffffu, s, o);
    float mu = s * (1.f / 128.f);
    float dx = acc.x - mu, dy = acc.y - mu, dz = acc.z - mu, dw = acc.w - mu;
    float q = dx * dx + dy * dy + dz * dz + dw * dw;
#pragma unroll
    for (int o = 16; o > 0; o >>= 1) q += __shfl_xor_sync(0xffffffffu, q, o);
    float rs = rsqrtf(q * (1.f / 128.f) + LN_EPS);

    float4 gm = reinterpret_cast<const float4*>(gamma)[lane];
    float4 bt = reinterpret_cast<const float4*>(beta)[lane];
    float4 r  = reinterpret_cast<const float4*>(g_h + (size_t)node * HID)[lane];
    float4 o;
    o.x = fmaxf(dx * rs * gm.x + bt.x, 0.f) + r.x;
    o.y = fmaxf(dy * rs * gm.y + bt.y, 0.f) + r.y;
    o.z = fmaxf(dz * rs * gm.z + bt.z, 0.f) + r.z;
    o.w = fmaxf(dw * rs * gm.w + bt.w, 0.f) + r.w;
    reinterpret_cast<float4*>(g_h + (size_t)node * HID)[lane] = o;
}

// ---------------- sorted-batch segmented pooling -----------------------------
#define POOL_RPB 128
__global__ __launch_bounds__(128) void k_pool(const int* __restrict__ batch) {
    int t  = threadIdx.x;                      // feature column
    int r0 = blockIdx.x * POOL_RPB;
    int r1 = min(r0 + POOL_RPB, N_NODES);
    if (r0 >= N_NODES) return;
    float acc = 0.f, cacc = 0.f;
    int gcur = batch[r0];
    for (int r = r0; r < r1; ++r) {
        int g = batch[r];
        if (g != gcur) {
            atomicAdd(&g_pooled[gcur * HID + t], acc);
            if (t == 0) atomicAdd(&g_cnt[gcur], cacc);
            acc = 0.f; cacc = 0.f; gcur = g;
        }
        acc  += g_h[(size_t)r * HID + t];
        cacc += 1.f;
    }
    atomicAdd(&g_pooled[gcur * HID + t], acc);
    if (t == 0) atomicAdd(&g_cnt[gcur], cacc);
}

// ---------------- final MLP --------------------------------------------------
__global__ __launch_bounds__(64) void k_mlp(const float* __restrict__ W1,
                                            const float* __restrict__ b1,
                                            const float* __restrict__ W2,
                                            const float* __restrict__ b2,
                                            float* __restrict__ out) {
    __shared__ float sp[128];
    __shared__ float part[2];
    int g = blockIdx.x, t = threadIdx.x;
    float inv = 1.f / fmaxf(g_cnt[g], 1.f);
    sp[t]      = g_pooled[g * HID + t] * inv;
    sp[t + 64] = g_pooled[g * HID + 64 + t] * inv;
    __syncthreads();
    float a = b1[t];
#pragma unroll 8
    for (int k = 0; k < 128; ++k) a += sp[k] * W1[t * 128 + k];
    a = fmaxf(a, 0.f);
    float v = a * W2[t];
#pragma unroll
    for (int o = 16; o > 0; o >>= 1) v += __shfl_xor_sync(0xffffffffu, v, o);
    if ((t & 31) == 0) part[t >> 5] = v;
    __syncthreads();
    if (t == 0) out[g] = part[0] + part[1] + b2[0];
}

// ---------------- launch -----------------------------------------------------
extern "C" void kernel_launch(void* const* d_in, const int* in_sizes, int n_in,
                              void* d_out, int out_size) {
    const float* x     = (const float*)d_in[0];
    const int*   ei    = (const int*)  d_in[1];
    const int*   batch = (const int*)  d_in[2];
    const float* W_in  = (const float*)d_in[3];
    const float* b_in  = (const float*)d_in[4];
    const float* Wc    = (const float*)d_in[5];
    const float* bc    = (const float*)d_in[6];
    const float* gamma = (const float*)d_in[7];
    const float* beta  = (const float*)d_in[8];
    const float* W1    = (const float*)d_in[9];
    const float* b1    = (const float*)d_in[10];
    const float* W2    = (const float*)d_in[11];
    const float* b2    = (const float*)d_in[12];
    float* out = (float*)d_out;

    const int* src = ei;
    const int* dst = ei + N_EDGES;

    k_init<<<(NUM_GRAPHS * HID + 255) / 256, 256>>>();
    k_hist<<<(N_EDGES + 255) / 256, 256>>>(dst);
    k_scan<<<1, 1024>>>();
    k_fill<<<(N_EDGES + 255) / 256, 256>>>(src, dst);

    int gemm_blocks = (N_NODES + 127) / 128;
    k_gemm<<<gemm_blocks, 256>>>(x, W_in, b_in, N_NODES, 0);

    int gl_blocks = (N_NODES * 32 + 255) / 256;
    for (int l = 0; l < N_LAYERS; ++l) {
        k_gemm<<<gemm_blocks, 256>>>((const float*)0, Wc + (size_t)l * HID * HID,
                                     (const float*)0, N_NODES, 1);
        k_gatherln<<<gl_blocks, 256>>>(bc + l * HID, gamma + l * HID, beta + l * HID);
    }

    k_pool<<<(N_NODES + POOL_RPB - 1) / POOL_RPB, 128>>>(batch);
    k_mlp<<<NUM_GRAPHS, 64>>>(W1, b1, W2, b2, out);
}

// round 4
// speedup vs baseline: 1.6811x; 1.0703x over previous
#include <cuda_runtime.h>
#include <cstdint>

#define N_NODES 50000
#define N_EDGES 800000
#define HID 128
#define NUM_GRAPHS 500
#define N_LAYERS 3
#define LN_EPS 1e-5f

// ---------------- scratch (device globals) ----------------------------------
__device__ float g_deg[N_NODES];                      // dinv
__device__ int   g_indeg[N_NODES];
__device__ int   g_off[N_NODES + 1];
__device__ int   g_cur[N_NODES];
__device__ int2  g_epack[N_EDGES];                    // {src, bits(weight)}
__device__ float g_h[(size_t)N_NODES * HID];
__device__ float g_hw[(size_t)N_NODES * HID];

// ---------------- init (indeg only) ------------------------------------------
__global__ void k_init() {
    int i = blockIdx.x * blockDim.x + threadIdx.x;
    if (i < N_NODES) g_indeg[i] = 0;
}

// ---------------- in-degree histogram ----------------------------------------
__global__ void k_hist(const int* __restrict__ dst) {
    int i = blockIdx.x * blockDim.x + threadIdx.x;
    if (i < N_EDGES) atomicAdd(&g_indeg[dst[i]], 1);
}

// ---------------- single-block scan: offsets + cursors + dinv -----------------
__global__ __launch_bounds__(1024) void k_scan() {
    __shared__ int warp_sums[32];
    __shared__ int s_carry;
    int t = threadIdx.x, lane = t & 31, wid = t >> 5;
    if (t == 0) s_carry = 0;
    __syncthreads();
    for (int base = 0; base < N_NODES; base += 1024) {
        int i = base + t;
        int v = (i < N_NODES) ? g_indeg[i] : 0;
        int x = v;
#pragma unroll
        for (int o = 1; o < 32; o <<= 1) {
            int y = __shfl_up_sync(0xffffffffu, x, o);
            if (lane >= o) x += y;
        }
        if (lane == 31) warp_sums[wid] = x;
        __syncthreads();
        if (wid == 0) {
            int s = warp_sums[lane];
#pragma unroll
            for (int o = 1; o < 32; o <<= 1) {
                int y = __shfl_up_sync(0xffffffffu, s, o);
                if (lane >= o) s += y;
            }
            warp_sums[lane] = s;
        }
        __syncthreads();
        int off = s_carry + (wid ? warp_sums[wid - 1] : 0) + (x - v);
        if (i < N_NODES) {
            g_off[i] = off;
            g_cur[i] = off;
            g_deg[i] = rsqrtf((float)v + 1.f);
        }
        __syncthreads();
        if (t == 0) s_carry += warp_sums[31];
        __syncthreads();
    }
    if (t == 0) g_off[N_NODES] = s_carry;
}

// ---------------- CSR bucket fill (packed) ------------------------------------
__global__ void k_fill(const int* __restrict__ src, const int* __restrict__ dst) {
    int e = blockIdx.x * blockDim.x + threadIdx.x;
    if (e >= N_EDGES) return;
    int s = src[e], d = dst[e];
    int slot = atomicAdd(&g_cur[d], 1);
    g_epack[slot] = make_int2(s, __float_as_int(g_deg[s] * g_deg[d]));
}

// ---------------- GEMM: C[M,128] = A[M,128] @ W[128,128]^T (+bias) -----------
#define KC 16
#define WSTR 132
#define ASTR 36

__global__ __launch_bounds__(256, 2) void k_gemm(
    const float* A_ext, const float* __restrict__ W,
    const float* __restrict__ bias, int M, int mode)
{
    __shared__ float Ws[KC * WSTR];
    __shared__ float As2[128 * ASTR];

    const float* A = (mode == 0) ? A_ext : g_h;
    float* C = (mode == 0) ? g_h : g_hw;

    int t  = threadIdx.x;
    int tx = t & 15;
    int ty = t >> 4;
    int row0 = blockIdx.x * 128;
    int c0a = tx * 4;
    int c0b = 64 + tx * 4;
    int r0 = ty * 8;

    unsigned long long acc[8][4];
#pragma unroll
    for (int i = 0; i < 8; i++) {
        acc[i][0] = 0ull; acc[i][1] = 0ull; acc[i][2] = 0ull; acc[i][3] = 0ull;
    }

    for (int kc = 0; kc < 128; kc += KC) {
        for (int i = t; i < KC * 128; i += 256) {
            int n = i >> 4;
            int k = i & 15;
            Ws[k * WSTR + n] = W[n * 128 + kc + k];
        }
        for (int i = t; i < 128 * (KC / 4); i += 256) {
            int r  = i >> 2;
            int kq = i & 3;
            int gr = row0 + r;
            float4 v = make_float4(0.f, 0.f, 0.f, 0.f);
            if (gr < M)
                v = reinterpret_cast<const float4*>(A + (size_t)gr * 128 + kc)[kq];
            float* p = As2 + r * ASTR + kq * 8;
            reinterpret_cast<float4*>(p)[0] = make_float4(v.x, v.x, v.y, v.y);
            reinterpret_cast<float4*>(p)[1] = make_float4(v.z, v.z, v.w, v.w);
        }
        __syncthreads();

#pragma unroll
        for (int k = 0; k < KC; k += 2) {
            ulonglong2 wa0 = *reinterpret_cast<const ulonglong2*>(&Ws[k * WSTR + c0a]);
            ulonglong2 wb0 = *reinterpret_cast<const ulonglong2*>(&Ws[k * WSTR + c0b]);
            ulonglong2 wa1 = *reinterpret_cast<const ulonglong2*>(&Ws[(k + 1) * WSTR + c0a]);
            ulonglong2 wb1 = *reinterpret_cast<const ulonglong2*>(&Ws[(k + 1) * WSTR + c0b]);
#pragma unroll
            for (int i = 0; i < 8; ++i) {
                ulonglong2 aa = *reinterpret_cast<const ulonglong2*>(
                    As2 + (r0 + i) * ASTR + k * 2);
                asm("fma.rn.f32x2 %0, %1, %2, %0;" : "+l"(acc[i][0]) : "l"(aa.x), "l"(wa0.x));
                asm("fma.rn.f32x2 %0, %1, %2, %0;" : "+l"(acc[i][1]) : "l"(aa.x), "l"(wa0.y));
                asm("fma.rn.f32x2 %0, %1, %2, %0;" : "+l"(acc[i][2]) : "l"(aa.x), "l"(wb0.x));
                asm("fma.rn.f32x2 %0, %1, %2, %0;" : "+l"(acc[i][3]) : "l"(aa.x), "l"(wb0.y));
                asm("fma.rn.f32x2 %0, %1, %2, %0;" : "+l"(acc[i][0]) : "l"(aa.y), "l"(wa1.x));
                asm("fma.rn.f32x2 %0, %1, %2, %0;" : "+l"(acc[i][1]) : "l"(aa.y), "l"(wa1.y));
                asm("fma.rn.f32x2 %0, %1, %2, %0;" : "+l"(acc[i][2]) : "l"(aa.y), "l"(wb1.x));
                asm("fma.rn.f32x2 %0, %1, %2, %0;" : "+l"(acc[i][3]) : "l"(aa.y), "l"(wb1.y));
            }
        }
        __syncthreads();
    }

    float4 bva = make_float4(0.f, 0.f, 0.f, 0.f);
    float4 bvb = make_float4(0.f, 0.f, 0.f, 0.f);
    if (bias) {
        bva = *reinterpret_cast<const float4*>(bias + c0a);
        bvb = *reinterpret_cast<const float4*>(bias + c0b);
    }

#pragma unroll
    for (int i = 0; i < 8; ++i) {
        int gr = row0 + r0 + i;
        if (gr >= M) break;
        float4 va, vb;
        asm("mov.b64 {%0,%1}, %2;" : "=f"(va.x), "=f"(va.y) : "l"(acc[i][0]));
        asm("mov.b64 {%0,%1}, %2;" : "=f"(va.z), "=f"(va.w) : "l"(acc[i][1]));
        asm("mov.b64 {%0,%1}, %2;" : "=f"(vb.x), "=f"(vb.y) : "l"(acc[i][2]));
        asm("mov.b64 {%0,%1}, %2;" : "=f"(vb.z), "=f"(vb.w) : "l"(acc[i][3]));
        va.x += bva.x; va.y += bva.y; va.z += bva.z; va.w += bva.w;
        vb.x += bvb.x; vb.y += bvb.y; vb.z += bvb.z; vb.w += bvb.w;
        float* crow = C + (size_t)gr * 128;
        *reinterpret_cast<float4*>(crow + c0a) = va;
        *reinterpret_cast<float4*>(crow + c0b) = vb;
    }
}

// ---------------- fused gather + self-loop + LN + ReLU + residual ------------
// warp per dst node, 8 edges in flight.
#define EDGE4(E)                                                                \
    {                                                                           \
        int2 p0 = g_epack[E], p1 = g_epack[(E) + 1];                            \
        int2 p2 = g_epack[(E) + 2], p3 = g_epack[(E) + 3];                      \
        float4 v0 = reinterpret_cast<const float4*>(g_hw + (size_t)p0.x * HID)[lane]; \
        float4 v1 = reinterpret_cast<const float4*>(g_hw + (size_t)p1.x * HID)[lane]; \
        float4 v2 = reinterpret_cast<const float4*>(g_hw + (size_t)p2.x * HID)[lane]; \
        float4 v3 = reinterpret_cast<const float4*>(g_hw + (size_t)p3.x * HID)[lane]; \
        float w0 = __int_as_float(p0.y), w1 = __int_as_float(p1.y);             \
        float w2 = __int_as_float(p2.y), w3 = __int_as_float(p3.y);             \
        acc.x += w0 * v0.x + w1 * v1.x + w2 * v2.x + w3 * v3.x;                 \
        acc.y += w0 * v0.y + w1 * v1.y + w2 * v2.y + w3 * v3.y;                 \
        acc.z += w0 * v0.z + w1 * v1.z + w2 * v2.z + w3 * v3.z;                 \
        acc.w += w0 * v0.w + w1 * v1.w + w2 * v2.w + w3 * v3.w;                 \
    }

__global__ __launch_bounds__(256) void k_gatherln(
    const float* __restrict__ bc,
    const float* __restrict__ gamma, const float* __restrict__ beta)
{
    int node = (blockIdx.x * blockDim.x + threadIdx.x) >> 5;
    int lane = threadIdx.x & 31;
    if (node >= N_NODES) return;

    int e0 = g_off[node], e1 = g_off[node + 1];
    float dv = g_deg[node];
    float sn = dv * dv;

    float4 hv  = reinterpret_cast<const float4*>(g_hw + (size_t)node * HID)[lane];
    float4 bcv = reinterpret_cast<const float4*>(bc)[lane];
    float4 acc = make_float4(hv.x * sn + bcv.x, hv.y * sn + bcv.y,
                             hv.z * sn + bcv.z, hv.w * sn + bcv.w);

    int e = e0;
#pragma unroll 1
    for (; e + 8 <= e1; e += 8) {
        EDGE4(e)
        EDGE4(e + 4)
    }
    if (e + 4 <= e1) { EDGE4(e) e += 4; }
#pragma unroll 1
    for (; e < e1; ++e) {
        int2 p = g_epack[e];
        float w = __int_as_float(p.y);
        float4 v = reinterpret_cast<const float4*>(g_hw + (size_t)p.x * HID)[lane];
        acc.x += w * v.x; acc.y += w * v.y;
        acc.z += w * v.z; acc.w += w * v.w;
    }

    // LayerNorm over 128 features
    float s = acc.x + acc.y + acc.z + acc.w;
#pragma unroll
    for (int o = 16; o > 0; o >>= 1) s += __shfl_xor_sync(0xffffffffu, s, o);
    float mu = s * (1.f / 128.f);
    float dx = acc.x - mu, dy = acc.y - mu, dz = acc.z - mu, dw = acc.w - mu;
    float q = dx * dx + dy * dy + dz * dz + dw * dw;
#pragma unroll
    for (int o = 16; o > 0; o >>= 1) q += __shfl_xor_sync(0xffffffffu, q, o);
    float rs = rsqrtf(q * (1.f / 128.f) + LN_EPS);

    float4 gm = reinterpret_cast<const float4*>(gamma)[lane];
    float4 bt = reinterpret_cast<const float4*>(beta)[lane];
    float4 r  = reinterpret_cast<const float4*>(g_h + (size_t)node * HID)[lane];
    float4 o;
    o.x = fmaxf(dx * rs * gm.x + bt.x, 0.f) + r.x;
    o.y = fmaxf(dy * rs * gm.y + bt.y, 0.f) + r.y;
    o.z = fmaxf(dz * rs * gm.z + bt.z, 0.f) + r.z;
    o.w = fmaxf(dw * rs * gm.w + bt.w, 0.f) + r.w;
    reinterpret_cast<float4*>(g_h + (size_t)node * HID)[lane] = o;
}

// ---------------- fused pool + MLP (block per graph, atomic-free) ------------
__global__ __launch_bounds__(128) void k_poolmlp(
    const int* __restrict__ batch,
    const float* __restrict__ W1, const float* __restrict__ b1,
    const float* __restrict__ W2, const float* __restrict__ b2,
    float* __restrict__ out)
{
    __shared__ float sp[128];
    __shared__ float part[2];
    int g = blockIdx.x, t = threadIdx.x;

    // lower_bound(batch, g) and lower_bound(batch, g+1) on sorted batch
    int lo = 0, hi = N_NODES;
    while (lo < hi) { int m = (lo + hi) >> 1; if (batch[m] < g) lo = m + 1; else hi = m; }
    int start = lo;
    hi = N_NODES;
    while (lo < hi) { int m = (lo + hi) >> 1; if (batch[m] < g + 1) lo = m + 1; else hi = m; }
    int end = lo;

    float acc = 0.f;
    for (int r = start; r < end; ++r) acc += g_h[(size_t)r * HID + t];
    float inv = 1.f / fmaxf((float)(end - start), 1.f);
    sp[t] = acc * inv;
    __syncthreads();

    if (t < 64) {
        float a = b1[t];
#pragma unroll 8
        for (int k = 0; k < 128; ++k) a += sp[k] * W1[t * 128 + k];
        a = fmaxf(a, 0.f);
        float v = a * W2[t];
#pragma unroll
        for (int o = 16; o > 0; o >>= 1) v += __shfl_xor_sync(0xffffffffu, v, o);
        if ((t & 31) == 0) part[t >> 5] = v;
    }
    __syncthreads();
    if (t == 0) out[g] = part[0] + part[1] + b2[0];
}

// ---------------- launch -----------------------------------------------------
extern "C" void kernel_launch(void* const* d_in, const int* in_sizes, int n_in,
                              void* d_out, int out_size) {
    const float* x     = (const float*)d_in[0];
    const int*   ei    = (const int*)  d_in[1];
    const int*   batch = (const int*)  d_in[2];
    const float* W_in  = (const float*)d_in[3];
    const float* b_in  = (const float*)d_in[4];
    const float* Wc    = (const float*)d_in[5];
    const float* bc    = (const float*)d_in[6];
    const float* gamma = (const float*)d_in[7];
    const float* beta  = (const float*)d_in[8];
    const float* W1    = (const float*)d_in[9];
    const float* b1    = (const float*)d_in[10];
    const float* W2    = (const float*)d_in[11];
    const float* b2    = (const float*)d_in[12];
    float* out = (float*)d_out;

    const int* src = ei;
    const int* dst = ei + N_EDGES;

    k_init<<<(N_NODES + 255) / 256, 256>>>();
    k_hist<<<(N_EDGES + 255) / 256, 256>>>(dst);
    k_scan<<<1, 1024>>>();
    k_fill<<<(N_EDGES + 255) / 256, 256>>>(src, dst);

    int gemm_blocks = (N_NODES + 127) / 128;
    k_gemm<<<gemm_blocks, 256>>>(x, W_in, b_in, N_NODES, 0);

    int gl_blocks = (N_NODES * 32 + 255) / 256;
    for (int l = 0; l < N_LAYERS; ++l) {
        k_gemm<<<gemm_blocks, 256>>>((const float*)0, Wc + (size_t)l * HID * HID,
                                     (const float*)0, N_NODES, 1);
        k_gatherln<<<gl_blocks, 256>>>(bc + l * HID, gamma + l * HID, beta + l * HID);
    }

    k_poolmlp<<<NUM_GRAPHS, 128>>>(batch, W1, b1, W2, b2, out);
}

// round 6
// speedup vs baseline: 2.1634x; 1.2869x over previous
#include <cuda_runtime.h>
#include <cuda_bf16.h>
#include <cstdint>

#define N_NODES 50000
#define N_EDGES 800000
#define HID 128
#define NUM_GRAPHS 500
#define N_LAYERS 3
#define LN_EPS 1e-5f

// ---------------- scratch (device globals) ----------------------------------
__device__ float g_deg[N_NODES];                      // dinv
__device__ int   g_indeg[N_NODES];
__device__ int   g_off[N_NODES + 1];
__device__ int   g_cur[N_NODES];
__device__ int2  g_epack[N_EDGES];                    // {src, bits(weight)}
__device__ float g_h[(size_t)N_NODES * HID];
__device__ float g_hw[(size_t)N_NODES * HID];
// per mat: hi 8192 u32 (n*64 + kpair), lo 8192 u32
__device__ uint32_t g_wbf[4 * 16384];

// ---------------- bf16 hi/lo pack helper -------------------------------------
__device__ __forceinline__ void pack_hilo(float x0, float x1,
                                          uint32_t& hp, uint32_t& lp) {
    unsigned short h0 = __bfloat16_as_ushort(__float2bfloat16(x0));
    unsigned short h1 = __bfloat16_as_ushort(__float2bfloat16(x1));
    float r0 = x0 - __uint_as_float((uint32_t)h0 << 16);
    float r1 = x1 - __uint_as_float((uint32_t)h1 << 16);
    unsigned short l0 = __bfloat16_as_ushort(__float2bfloat16(r0));
    unsigned short l1 = __bfloat16_as_ushort(__float2bfloat16(r1));
    hp = (uint32_t)h0 | ((uint32_t)h1 << 16);
    lp = (uint32_t)l0 | ((uint32_t)l1 << 16);
}

#define MMA_BF16(d, a, bv0, bv1)                                                \
    asm volatile("mma.sync.aligned.m16n8k16.row.col.f32.bf16.bf16.f32 "         \
        "{%0,%1,%2,%3}, {%4,%5,%6,%7}, {%8,%9}, {%0,%1,%2,%3};"                 \
        : "+f"((d)[0]), "+f"((d)[1]), "+f"((d)[2]), "+f"((d)[3])                \
        : "r"((a)[0]), "r"((a)[1]), "r"((a)[2]), "r"((a)[3]),                   \
          "r"(bv0), "r"(bv1));

// ---------------- init (indeg only) ------------------------------------------
__global__ void k_init() {
    int i = blockIdx.x * blockDim.x + threadIdx.x;
    if (i < N_NODES) g_indeg[i] = 0;
}

// ---------------- in-degree histogram ----------------------------------------
__global__ void k_hist(const int* __restrict__ dst) {
    int i = blockIdx.x * blockDim.x + threadIdx.x;
    if (i < N_EDGES) atomicAdd(&g_indeg[dst[i]], 1);
}

// ---------------- single-block scan: offsets + cursors + dinv -----------------
__global__ __launch_bounds__(1024) void k_scan() {
    __shared__ int warp_sums[32];
    __shared__ int s_carry;
    int t = threadIdx.x, lane = t & 31, wid = t >> 5;
    if (t == 0) s_carry = 0;
    __syncthreads();
    for (int base = 0; base < N_NODES; base += 1024) {
        int i = base + t;
        int v = (i < N_NODES) ? g_indeg[i] : 0;
        int x = v;
#pragma unroll
        for (int o = 1; o < 32; o <<= 1) {
            int y = __shfl_up_sync(0xffffffffu, x, o);
            if (lane >= o) x += y;
        }
        if (lane == 31) warp_sums[wid] = x;
        __syncthreads();
        if (wid == 0) {
            int s = warp_sums[lane];
#pragma unroll
            for (int o = 1; o < 32; o <<= 1) {
                int y = __shfl_up_sync(0xffffffffu, s, o);
                if (lane >= o) s += y;
            }
            warp_sums[lane] = s;
        }
        __syncthreads();
        int off = s_carry + (wid ? warp_sums[wid - 1] : 0) + (x - v);
        if (i < N_NODES) {
            g_off[i] = off;
            g_cur[i] = off;
            g_deg[i] = rsqrtf((float)v + 1.f);
        }
        __syncthreads();
        if (t == 0) s_carry += warp_sums[31];
        __syncthreads();
    }
    if (t == 0) g_off[N_NODES] = s_carry;
}

// ---------------- CSR bucket fill (packed) ------------------------------------
__global__ void k_fill(const int* __restrict__ src, const int* __restrict__ dst) {
    int e = blockIdx.x * blockDim.x + threadIdx.x;
    if (e >= N_EDGES) return;
    int s = src[e], d = dst[e];
    int slot = atomicAdd(&g_cur[d], 1);
    g_epack[slot] = make_int2(s, __float_as_int(g_deg[s] * g_deg[d]));
}

// ---------------- weight convert: fp32 -> linear bf16 hi/lo -------------------
// layout: g_wbf[mat*16384 + n*64 + kpair] (hi), +8192 (lo)
__global__ __launch_bounds__(128) void k_wconv(const float* __restrict__ W_in,
                                               const float* __restrict__ Wc) {
    int mat = blockIdx.x;                 // 0 = W_in, 1..3 = Wc[l]
    const float* W = (mat == 0) ? W_in : Wc + (size_t)(mat - 1) * 16384;
    int n = threadIdx.x;                  // output row (N dim)
    uint32_t* hi = g_wbf + (size_t)mat * 16384 + n * 64;
    uint32_t* lo = hi + 8192;
    const float2* wr = reinterpret_cast<const float2*>(W + (size_t)n * 128);
#pragma unroll
    for (int p = 0; p < 64; ++p) {
        float2 v = wr[p];
        pack_hilo(v.x, v.y, hi[p], lo[p]);
    }
}

// ---------------- tensor-core GEMM: C[M,128] = A[M,128] @ W^T (+bias) --------
// bf16x3 split via mma.sync m16n8k16 (sm_80 baseline feature).
// 128x128 block, 256 threads; warp = 32 rows x 64 cols.
// smem row stride 36 words -> fragment LDS are bank-conflict-free.
#define GSTR 36
#define GEMM_SMEM (4 * 128 * GSTR * 4)    // 73728 B

__global__ __launch_bounds__(256) void k_gemmmma(
    const float* A_ext, int mat, const float* __restrict__ bias, int M, int mode)
{
    extern __shared__ uint32_t sm[];
    uint32_t* AsHi = sm;
    uint32_t* AsLo = sm + 128 * GSTR;
    uint32_t* WsHi = sm + 2 * 128 * GSTR;
    uint32_t* WsLo = sm + 3 * 128 * GSTR;

    const float* A = (mode == 0) ? A_ext : g_h;
    float* C = (mode == 0) ? g_h : g_hw;

    int t = threadIdx.x;
    int lane = t & 31, w = t >> 5;
    int wm = w >> 1;                      // 0..3 -> rows wm*32
    int wn = w & 1;                       // 0..1 -> cols wn*64
    int lr = lane >> 2, lq = lane & 3;
    int row0 = blockIdx.x * 128;

    int cr = t >> 1;                      // convert row 0..127
    int ch = t & 1;                       // k half of chunk

    float acc[2][8][4];
#pragma unroll
    for (int i = 0; i < 2; ++i)
#pragma unroll
        for (int j = 0; j < 8; ++j)
#pragma unroll
            for (int q = 0; q < 4; ++q) acc[i][j][q] = 0.f;

    const uint32_t* gwH = g_wbf + (size_t)mat * 16384;

#pragma unroll 1
    for (int c = 0; c < 2; ++c) {
        // ---- stage A chunk (fp32 -> bf16 hi/lo), rows cr, k c*64+ch*32.. ----
        {
            int gr = row0 + cr;
            const float4* arow = (gr < M)
                ? reinterpret_cast<const float4*>(A + (size_t)gr * 128 + c * 64 + ch * 32)
                : (const float4*)0;
            uint4* dh = reinterpret_cast<uint4*>(AsHi + cr * GSTR + ch * 16);
            uint4* dl = reinterpret_cast<uint4*>(AsLo + cr * GSTR + ch * 16);
#pragma unroll
            for (int i = 0; i < 4; ++i) {
                float4 v0 = arow ? arow[2 * i] : make_float4(0.f, 0.f, 0.f, 0.f);
                float4 v1 = arow ? arow[2 * i + 1] : make_float4(0.f, 0.f, 0.f, 0.f);
                uint32_t hp0, lp0, hp1, lp1, hp2, lp2, hp3, lp3;
                pack_hilo(v0.x, v0.y, hp0, lp0);
                pack_hilo(v0.z, v0.w, hp1, lp1);
                pack_hilo(v1.x, v1.y, hp2, lp2);
                pack_hilo(v1.z, v1.w, hp3, lp3);
                dh[i] = make_uint4(hp0, hp1, hp2, hp3);
                dl[i] = make_uint4(lp0, lp1, lp2, lp3);
            }
            // ---- stage W chunk (pre-split, straight copy) ----
            const uint4* sH = reinterpret_cast<const uint4*>(
                gwH + cr * 64 + c * 32 + ch * 16);
            const uint4* sL = reinterpret_cast<const uint4*>(
                gwH + 8192 + cr * 64 + c * 32 + ch * 16);
            uint4* wh = reinterpret_cast<uint4*>(WsHi + cr * GSTR + ch * 16);
            uint4* wl = reinterpret_cast<uint4*>(WsLo + cr * GSTR + ch * 16);
#pragma unroll
            for (int i = 0; i < 4; ++i) { wh[i] = sH[i]; wl[i] = sL[i]; }
        }
        __syncthreads();

        // ---- 4 k-steps of 16 ----
#pragma unroll
        for (int s = 0; s < 4; ++s) {
            int w0 = s * 8 + lq;
            uint32_t ah[2][4], al[2][4];
#pragma unroll
            for (int tm = 0; tm < 2; ++tm) {
                int ra = (wm * 32 + tm * 16 + lr) * GSTR + w0;
                ah[tm][0] = AsHi[ra];
                ah[tm][1] = AsHi[ra + 8 * GSTR];
                ah[tm][2] = AsHi[ra + 4];
                ah[tm][3] = AsHi[ra + 8 * GSTR + 4];
                al[tm][0] = AsLo[ra];
                al[tm][1] = AsLo[ra + 8 * GSTR];
                al[tm][2] = AsLo[ra + 4];
                al[tm][3] = AsLo[ra + 8 * GSTR + 4];
            }
#pragma unroll
            for (int j = 0; j < 8; ++j) {
                int rb = (wn * 64 + j * 8 + lr) * GSTR + w0;
                uint32_t bh0 = WsHi[rb], bh1 = WsHi[rb + 4];
                uint32_t bl0 = WsLo[rb], bl1 = WsLo[rb + 4];
#pragma unroll
                for (int tm = 0; tm < 2; ++tm) {
                    MMA_BF16(acc[tm][j], ah[tm], bh0, bh1);
                    MMA_BF16(acc[tm][j], ah[tm], bl0, bl1);
                    MMA_BF16(acc[tm][j], al[tm], bh0, bh1);
                }
            }
        }
        __syncthreads();
    }

    // ---- epilogue ----
#pragma unroll
    for (int tm = 0; tm < 2; ++tm) {
        int row = row0 + wm * 32 + tm * 16 + lr;
#pragma unroll
        for (int j = 0; j < 8; ++j) {
            int col = wn * 64 + j * 8 + lq * 2;
            float bx = 0.f, by = 0.f;
            if (bias) {
                float2 bv = *reinterpret_cast<const float2*>(bias + col);
                bx = bv.x; by = bv.y;
            }
            if (row < M) {
                float2 v = make_float2(acc[tm][j][0] + bx, acc[tm][j][1] + by);
                *reinterpret_cast<float2*>(C + (size_t)row * 128 + col) = v;
            }
            if (row + 8 < M) {
                float2 v = make_float2(acc[tm][j][2] + bx, acc[tm][j][3] + by);
                *reinterpret_cast<float2*>(C + (size_t)(row + 8) * 128 + col) = v;
            }
        }
    }
}

// ---------------- fused gather + self-loop + LN + ReLU + residual ------------
#define EDGE4(E)                                                                \
    {                                                                           \
        int2 p0 = g_epack[E], p1 = g_epack[(E) + 1];                            \
        int2 p2 = g_epack[(E) + 2], p3 = g_epack[(E) + 3];                      \
        float4 v0 = reinterpret_cast<const float4*>(g_hw + (size_t)p0.x * HID)[lane]; \
        float4 v1 = reinterpret_cast<const float4*>(g_hw + (size_t)p1.x * HID)[lane]; \
        float4 v2 = reinterpret_cast<const float4*>(g_hw + (size_t)p2.x * HID)[lane]; \
        float4 v3 = reinterpret_cast<const float4*>(g_hw + (size_t)p3.x * HID)[lane]; \
        float w0 = __int_as_float(p0.y), w1 = __int_as_float(p1.y);             \
        float w2 = __int_as_float(p2.y), w3 = __int_as_float(p3.y);             \
        acc.x += w0 * v0.x + w1 * v1.x + w2 * v2.x + w3 * v3.x;                 \
        acc.y += w0 * v0.y + w1 * v1.y + w2 * v2.y + w3 * v3.y;                 \
        acc.z += w0 * v0.z + w1 * v1.z + w2 * v2.z + w3 * v3.z;                 \
        acc.w += w0 * v0.w + w1 * v1.w + w2 * v2.w + w3 * v3.w;                 \
    }

__global__ __launch_bounds__(256) void k_gatherln(
    const float* __restrict__ bc,
    const float* __restrict__ gamma, const float* __restrict__ beta)
{
    int node = (blockIdx.x * blockDim.x + threadIdx.x) >> 5;
    int lane = threadIdx.x & 31;
    if (node >= N_NODES) return;

    int e0 = g_off[node], e1 = g_off[node + 1];
    float dv = g_deg[node];
    float sn = dv * dv;

    float4 hv  = reinterpret_cast<const float4*>(g_hw + (size_t)node * HID)[lane];
    float4 bcv = reinterpret_cast<const float4*>(bc)[lane];
    float4 acc = make_float4(hv.x * sn + bcv.x, hv.y * sn + bcv.y,
                             hv.z * sn + bcv.z, hv.w * sn + bcv.w);

    int e = e0;
#pragma unroll 1
    for (; e + 8 <= e1; e += 8) {
        EDGE4(e)
        EDGE4(e + 4)
    }
    if (e + 4 <= e1) { EDGE4(e) e += 4; }
#pragma unroll 1
    for (; e < e1; ++e) {
        int2 p = g_epack[e];
        float w = __int_as_float(p.y);
        float4 v = reinterpret_cast<const float4*>(g_hw + (size_t)p.x * HID)[lane];
        acc.x += w * v.x; acc.y += w * v.y;
        acc.z += w * v.z; acc.w += w * v.w;
    }

    float s = acc.x + acc.y + acc.z + acc.w;
#pragma unroll
    for (int o = 16; o > 0; o >>= 1) s += __shfl_xor_sync(0xffffffffu, s, o);
    float mu = s * (1.f / 128.f);
    float dx = acc.x - mu, dy = acc.y - mu, dz = acc.z - mu, dw = acc.w - mu;
    float q = dx * dx + dy * dy + dz * dz + dw * dw;
#pragma unroll
    for (int o = 16; o > 0; o >>= 1) q += __shfl_xor_sync(0xffffffffu, q, o);
    float rs = rsqrtf(q * (1.f / 128.f) + LN_EPS);

    float4 gm = reinterpret_cast<const float4*>(gamma)[lane];
    float4 bt = reinterpret_cast<const float4*>(beta)[lane];
    float4 r  = reinterpret_cast<const float4*>(g_h + (size_t)node * HID)[lane];
    float4 o;
    o.x = fmaxf(dx * rs * gm.x + bt.x, 0.f) + r.x;
    o.y = fmaxf(dy * rs * gm.y + bt.y, 0.f) + r.y;
    o.z = fmaxf(dz * rs * gm.z + bt.z, 0.f) + r.z;
    o.w = fmaxf(dw * rs * gm.w + bt.w, 0.f) + r.w;
    reinterpret_cast<float4*>(g_h + (size_t)node * HID)[lane] = o;
}

// ---------------- fused pool + MLP (block per graph, atomic-free) ------------
__global__ __launch_bounds__(128) void k_poolmlp(
    const int* __restrict__ batch,
    const float* __restrict__ W1, const float* __restrict__ b1,
    const float* __restrict__ W2, const float* __restrict__ b2,
    float* __restrict__ out)
{
    __shared__ float sp[128];
    __shared__ float part[2];
    int g = blockIdx.x, t = threadIdx.x;

    int lo = 0, hi = N_NODES;
    while (lo < hi) { int m = (lo + hi) >> 1; if (batch[m] < g) lo = m + 1; else hi = m; }
    int start = lo;
    hi = N_NODES;
    while (lo < hi) { int m = (lo + hi) >> 1; if (batch[m] < g + 1) lo = m + 1; else hi = m; }
    int end = lo;

    float acc = 0.f;
    for (int r = start; r < end; ++r) acc += g_h[(size_t)r * HID + t];
    float inv = 1.f / fmaxf((float)(end - start), 1.f);
    sp[t] = acc * inv;
    __syncthreads();

    if (t < 64) {
        float a = b1[t];
#pragma unroll 8
        for (int k = 0; k < 128; ++k) a += sp[k] * W1[t * 128 + k];
        a = fmaxf(a, 0.f);
        float v = a * W2[t];
#pragma unroll
        for (int o = 16; o > 0; o >>= 1) v += __shfl_xor_sync(0xffffffffu, v, o);
        if ((t & 31) == 0) part[t >> 5] = v;
    }
    __syncthreads();
    if (t == 0) out[g] = part[0] + part[1] + b2[0];
}

// ---------------- launch -----------------------------------------------------
extern "C" void kernel_launch(void* const* d_in, const int* in_sizes, int n_in,
                              void* d_out, int out_size) {
    const float* x     = (const float*)d_in[0];
    const int*   ei    = (const int*)  d_in[1];
    const int*   batch = (const int*)  d_in[2];
    const float* W_in  = (const float*)d_in[3];
    const float* b_in  = (const float*)d_in[4];
    const float* Wc    = (const float*)d_in[5];
    const float* bc    = (const float*)d_in[6];
    const float* gamma = (const float*)d_in[7];
    const float* beta  = (const float*)d_in[8];
    const float* W1    = (const float*)d_in[9];
    const float* b1    = (const float*)d_in[10];
    const float* W2    = (const float*)d_in[11];
    const float* b2    = (const float*)d_in[12];
    float* out = (float*)d_out;

    const int* src = ei;
    const int* dst = ei + N_EDGES;

    cudaFuncSetAttribute(k_gemmmma, cudaFuncAttributeMaxDynamicSharedMemorySize,
                         GEMM_SMEM);

    k_wconv<<<4, 128>>>(W_in, Wc);
    k_init<<<(N_NODES + 255) / 256, 256>>>();
    k_hist<<<(N_EDGES + 255) / 256, 256>>>(dst);
    k_scan<<<1, 1024>>>();
    k_fill<<<(N_EDGES + 255) / 256, 256>>>(src, dst);

    int gemm_blocks = (N_NODES + 127) / 128;   // 391
    k_gemmmma<<<gemm_blocks, 256, GEMM_SMEM>>>(x, 0, b_in, N_NODES, 0);

    int gl_blocks = (N_NODES * 32 + 255) / 256;
    for (int l = 0; l < N_LAYERS; ++l) {
        k_gemmmma<<<gemm_blocks, 256, GEMM_SMEM>>>((const float*)0, l + 1,
                                                   (const float*)0, N_NODES, 1);
        k_gatherln<<<gl_blocks, 256>>>(bc + l * HID, gamma + l * HID, beta + l * HID);
    }

    k_poolmlp<<<NUM_GRAPHS, 128>>>(batch, W1, b1, W2, b2, out);
}

// round 7
// speedup vs baseline: 2.4288x; 1.1227x over previous
#include <cuda_runtime.h>
#include <cuda_bf16.h>
#include <cstdint>

#define N_NODES 50000
#define N_EDGES 800000
#define HID 128
#define NUM_GRAPHS 500
#define N_LAYERS 3
#define LN_EPS 1e-5f

#define SCAN_BLK 256
#define SCAN_NB  ((N_NODES + SCAN_BLK - 1) / SCAN_BLK)   // 196

// ---------------- scratch (device globals) ----------------------------------
__device__ float g_deg[N_NODES];                      // dinv
__device__ int   g_indeg[N_NODES];
__device__ int   g_off[N_NODES + 1];
__device__ int   g_cur[N_NODES];
__device__ int   g_bsum[SCAN_NB];
__device__ int   g_bbase[SCAN_NB];
__device__ int2  g_epack[N_EDGES];                    // {src, bits(weight)}
__device__ float g_h[(size_t)N_NODES * HID];
__device__ float g_hw[(size_t)N_NODES * HID];
// per mat: hi 8192 u32 (n*64 + kpair), lo 8192 u32
__device__ uint32_t g_wbf[4 * 16384];

// ---------------- bf16 hi/lo pack helper -------------------------------------
__device__ __forceinline__ void pack_hilo(float x0, float x1,
                                          uint32_t& hp, uint32_t& lp) {
    unsigned short h0 = __bfloat16_as_ushort(__float2bfloat16(x0));
    unsigned short h1 = __bfloat16_as_ushort(__float2bfloat16(x1));
    float r0 = x0 - __uint_as_float((uint32_t)h0 << 16);
    float r1 = x1 - __uint_as_float((uint32_t)h1 << 16);
    unsigned short l0 = __bfloat16_as_ushort(__float2bfloat16(r0));
    unsigned short l1 = __bfloat16_as_ushort(__float2bfloat16(r1));
    hp = (uint32_t)h0 | ((uint32_t)h1 << 16);
    lp = (uint32_t)l0 | ((uint32_t)l1 << 16);
}

#define MMA_BF16(d, a, bv0, bv1)                                                \
    asm volatile("mma.sync.aligned.m16n8k16.row.col.f32.bf16.bf16.f32 "         \
        "{%0,%1,%2,%3}, {%4,%5,%6,%7}, {%8,%9}, {%0,%1,%2,%3};"                 \
        : "+f"((d)[0]), "+f"((d)[1]), "+f"((d)[2]), "+f"((d)[3])                \
        : "r"((a)[0]), "r"((a)[1]), "r"((a)[2]), "r"((a)[3]),                   \
          "r"(bv0), "r"(bv1));

// ---------------- init (indeg only) ------------------------------------------
__global__ void k_init() {
    int i = blockIdx.x * blockDim.x + threadIdx.x;
    if (i < N_NODES) g_indeg[i] = 0;
}

// ---------------- in-degree histogram ----------------------------------------
__global__ void k_hist(const int* __restrict__ dst) {
    int i = blockIdx.x * blockDim.x + threadIdx.x;
    if (i < N_EDGES) atomicAdd(&g_indeg[dst[i]], 1);
}

// ---------------- 3-phase full-chip scan --------------------------------------
// A: per-block reduce indeg -> g_bsum
__global__ __launch_bounds__(SCAN_BLK) void k_scanA() {
    __shared__ int ws[8];
    int t = threadIdx.x, lane = t & 31, wid = t >> 5;
    int i = blockIdx.x * SCAN_BLK + t;
    int v = (i < N_NODES) ? g_indeg[i] : 0;
    int s = v;
#pragma unroll
    for (int o = 16; o > 0; o >>= 1) s += __shfl_xor_sync(0xffffffffu, s, o);
    if (lane == 0) ws[wid] = s;
    __syncthreads();
    if (t < 8) {
        int x = ws[t];
#pragma unroll
        for (int o = 4; o > 0; o >>= 1) x += __shfl_xor_sync(0xffu, x, o);
        if (t == 0) g_bsum[blockIdx.x] = x;
    }
}

// B: exclusive scan of the block sums (single small block)
__global__ __launch_bounds__(256) void k_scanB() {
    __shared__ int ws[8];
    int t = threadIdx.x, lane = t & 31, wid = t >> 5;
    int v = (t < SCAN_NB) ? g_bsum[t] : 0;
    int x = v;
#pragma unroll
    for (int o = 1; o < 32; o <<= 1) {
        int y = __shfl_up_sync(0xffffffffu, x, o);
        if (lane >= o) x += y;
    }
    if (lane == 31) ws[wid] = x;
    __syncthreads();
    if (wid == 0 && lane < 8) {
        int s = ws[lane];
#pragma unroll
        for (int o = 1; o < 8; o <<= 1) {
            int y = __shfl_up_sync(0xffu, s, o);
            if (lane >= o) s += y;
        }
        ws[lane] = s;
    }
    __syncthreads();
    int incl = x + (wid ? ws[wid - 1] : 0);
    if (t < SCAN_NB) g_bbase[t] = incl - v;
    if (t == 255) g_off[N_NODES] = incl;
}

// C: intra-block exclusive scan + base; write off/cur/deg
__global__ __launch_bounds__(SCAN_BLK) void k_scanC() {
    __shared__ int ws[8];
    int t = threadIdx.x, lane = t & 31, wid = t >> 5;
    int i = blockIdx.x * SCAN_BLK + t;
    int v = (i < N_NODES) ? g_indeg[i] : 0;
    int x = v;
#pragma unroll
    for (int o = 1; o < 32; o <<= 1) {
        int y = __shfl_up_sync(0xffffffffu, x, o);
        if (lane >= o) x += y;
    }
    if (lane == 31) ws[wid] = x;
    __syncthreads();
    if (wid == 0 && lane < 8) {
        int s = ws[lane];
#pragma unroll
        for (int o = 1; o < 8; o <<= 1) {
            int y = __shfl_up_sync(0xffu, s, o);
            if (lane >= o) s += y;
        }
        ws[lane] = s;
    }
    __syncthreads();
    if (i < N_NODES) {
        int off = g_bbase[blockIdx.x] + (wid ? ws[wid - 1] : 0) + (x - v);
        g_off[i] = off;
        g_cur[i] = off;
        g_deg[i] = rsqrtf((float)v + 1.f);
    }
}

// ---------------- CSR bucket fill (packed) ------------------------------------
__global__ void k_fill(const int* __restrict__ src, const int* __restrict__ dst) {
    int e = blockIdx.x * blockDim.x + threadIdx.x;
    if (e >= N_EDGES) return;
    int s = src[e], d = dst[e];
    int slot = atomicAdd(&g_cur[d], 1);
    g_epack[slot] = make_int2(s, __float_as_int(g_deg[s] * g_deg[d]));
}

// ---------------- weight convert: fp32 -> linear bf16 hi/lo -------------------
__global__ __launch_bounds__(128) void k_wconv(const float* __restrict__ W_in,
                                               const float* __restrict__ Wc) {
    int mat = blockIdx.x;                 // 0 = W_in, 1..3 = Wc[l]
    const float* W = (mat == 0) ? W_in : Wc + (size_t)(mat - 1) * 16384;
    int n = threadIdx.x;                  // output row (N dim)
    uint32_t* hi = g_wbf + (size_t)mat * 16384 + n * 64;
    uint32_t* lo = hi + 8192;
    const float2* wr = reinterpret_cast<const float2*>(W + (size_t)n * 128);
#pragma unroll
    for (int p = 0; p < 64; ++p) {
        float2 v = wr[p];
        pack_hilo(v.x, v.y, hi[p], lo[p]);
    }
}

// ---------------- tensor-core GEMM: C[M,128] = A[M,128] @ W^T (+bias) --------
#define GSTR 36
#define GEMM_SMEM (4 * 128 * GSTR * 4)    // 73728 B

__global__ __launch_bounds__(256) void k_gemmmma(
    const float* A_ext, int mat, const float* __restrict__ bias, int M, int mode)
{
    extern __shared__ uint32_t sm[];
    uint32_t* AsHi = sm;
    uint32_t* AsLo = sm + 128 * GSTR;
    uint32_t* WsHi = sm + 2 * 128 * GSTR;
    uint32_t* WsLo = sm + 3 * 128 * GSTR;

    const float* A = (mode == 0) ? A_ext : g_h;
    float* C = (mode == 0) ? g_h : g_hw;

    int t = threadIdx.x;
    int lane = t & 31, w = t >> 5;
    int wm = w >> 1;
    int wn = w & 1;
    int lr = lane >> 2, lq = lane & 3;
    int row0 = blockIdx.x * 128;

    int cr = t >> 1;
    int ch = t & 1;

    float acc[2][8][4];
#pragma unroll
    for (int i = 0; i < 2; ++i)
#pragma unroll
        for (int j = 0; j < 8; ++j)
#pragma unroll
            for (int q = 0; q < 4; ++q) acc[i][j][q] = 0.f;

    const uint32_t* gwH = g_wbf + (size_t)mat * 16384;

#pragma unroll 1
    for (int c = 0; c < 2; ++c) {
        {
            int gr = row0 + cr;
            const float4* arow = (gr < M)
                ? reinterpret_cast<const float4*>(A + (size_t)gr * 128 + c * 64 + ch * 32)
                : (const float4*)0;
            uint4* dh = reinterpret_cast<uint4*>(AsHi + cr * GSTR + ch * 16);
            uint4* dl = reinterpret_cast<uint4*>(AsLo + cr * GSTR + ch * 16);
#pragma unroll
            for (int i = 0; i < 4; ++i) {
                float4 v0 = arow ? arow[2 * i] : make_float4(0.f, 0.f, 0.f, 0.f);
                float4 v1 = arow ? arow[2 * i + 1] : make_float4(0.f, 0.f, 0.f, 0.f);
                uint32_t hp0, lp0, hp1, lp1, hp2, lp2, hp3, lp3;
                pack_hilo(v0.x, v0.y, hp0, lp0);
                pack_hilo(v0.z, v0.w, hp1, lp1);
                pack_hilo(v1.x, v1.y, hp2, lp2);
                pack_hilo(v1.z, v1.w, hp3, lp3);
                dh[i] = make_uint4(hp0, hp1, hp2, hp3);
                dl[i] = make_uint4(lp0, lp1, lp2, lp3);
            }
            const uint4* sH = reinterpret_cast<const uint4*>(
                gwH + cr * 64 + c * 32 + ch * 16);
            const uint4* sL = reinterpret_cast<const uint4*>(
                gwH + 8192 + cr * 64 + c * 32 + ch * 16);
            uint4* wh = reinterpret_cast<uint4*>(WsHi + cr * GSTR + ch * 16);
            uint4* wl = reinterpret_cast<uint4*>(WsLo + cr * GSTR + ch * 16);
#pragma unroll
            for (int i = 0; i < 4; ++i) { wh[i] = sH[i]; wl[i] = sL[i]; }
        }
        __syncthreads();

#pragma unroll
        for (int s = 0; s < 4; ++s) {
            int w0 = s * 8 + lq;
            uint32_t ah[2][4], al[2][4];
#pragma unroll
            for (int tm = 0; tm < 2; ++tm) {
                int ra = (wm * 32 + tm * 16 + lr) * GSTR + w0;
                ah[tm][0] = AsHi[ra];
                ah[tm][1] = AsHi[ra + 8 * GSTR];
                ah[tm][2] = AsHi[ra + 4];
                ah[tm][3] = AsHi[ra + 8 * GSTR + 4];
                al[tm][0] = AsLo[ra];
                al[tm][1] = AsLo[ra + 8 * GSTR];
                al[tm][2] = AsLo[ra + 4];
                al[tm][3] = AsLo[ra + 8 * GSTR + 4];
            }
#pragma unroll
            for (int j = 0; j < 8; ++j) {
                int rb = (wn * 64 + j * 8 + lr) * GSTR + w0;
                uint32_t bh0 = WsHi[rb], bh1 = WsHi[rb + 4];
                uint32_t bl0 = WsLo[rb], bl1 = WsLo[rb + 4];
#pragma unroll
                for (int tm = 0; tm < 2; ++tm) {
                    MMA_BF16(acc[tm][j], ah[tm], bh0, bh1);
                    MMA_BF16(acc[tm][j], ah[tm], bl0, bl1);
                    MMA_BF16(acc[tm][j], al[tm], bh0, bh1);
                }
            }
        }
        __syncthreads();
    }

#pragma unroll
    for (int tm = 0; tm < 2; ++tm) {
        int row = row0 + wm * 32 + tm * 16 + lr;
#pragma unroll
        for (int j = 0; j < 8; ++j) {
            int col = wn * 64 + j * 8 + lq * 2;
            float bx = 0.f, by = 0.f;
            if (bias) {
                float2 bv = *reinterpret_cast<const float2*>(bias + col);
                bx = bv.x; by = bv.y;
            }
            if (row < M) {
                float2 v = make_float2(acc[tm][j][0] + bx, acc[tm][j][1] + by);
                *reinterpret_cast<float2*>(C + (size_t)row * 128 + col) = v;
            }
            if (row + 8 < M) {
                float2 v = make_float2(acc[tm][j][2] + bx, acc[tm][j][3] + by);
                *reinterpret_cast<float2*>(C + (size_t)(row + 8) * 128 + col) = v;
            }
        }
    }
}

// ---------------- fused gather + self-loop + LN + ReLU + residual ------------
#define EDGE4(E)                                                                \
    {                                                                           \
        int2 p0 = g_epack[E], p1 = g_epack[(E) + 1];                            \
        int2 p2 = g_epack[(E) + 2], p3 = g_epack[(E) + 3];                      \
        float4 v0 = reinterpret_cast<const float4*>(g_hw + (size_t)p0.x * HID)[lane]; \
        float4 v1 = reinterpret_cast<const float4*>(g_hw + (size_t)p1.x * HID)[lane]; \
        float4 v2 = reinterpret_cast<const float4*>(g_hw + (size_t)p2.x * HID)[lane]; \
        float4 v3 = reinterpret_cast<const float4*>(g_hw + (size_t)p3.x * HID)[lane]; \
        float w0 = __int_as_float(p0.y), w1 = __int_as_float(p1.y);             \
        float w2 = __int_as_float(p2.y), w3 = __int_as_float(p3.y);             \
        acc.x += w0 * v0.x + w1 * v1.x + w2 * v2.x + w3 * v3.x;                 \
        acc.y += w0 * v0.y + w1 * v1.y + w2 * v2.y + w3 * v3.y;                 \
        acc.z += w0 * v0.z + w1 * v1.z + w2 * v2.z + w3 * v3.z;                 \
        acc.w += w0 * v0.w + w1 * v1.w + w2 * v2.w + w3 * v3.w;                 \
    }

__global__ __launch_bounds__(256) void k_gatherln(
    const float* __restrict__ bc,
    const float* __restrict__ gamma, const float* __restrict__ beta)
{
    int node = (blockIdx.x * blockDim.x + threadIdx.x) >> 5;
    int lane = threadIdx.x & 31;
    if (node >= N_NODES) return;

    int e0 = g_off[node], e1 = g_off[node + 1];
    float dv = g_deg[node];
    float sn = dv * dv;

    float4 hv  = reinterpret_cast<const float4*>(g_hw + (size_t)node * HID)[lane];
    float4 bcv = reinterpret_cast<const float4*>(bc)[lane];
    float4 acc = make_float4(hv.x * sn + bcv.x, hv.y * sn + bcv.y,
                             hv.z * sn + bcv.z, hv.w * sn + bcv.w);

    int e = e0;
#pragma unroll 1
    for (; e + 8 <= e1; e += 8) {
        EDGE4(e)
        EDGE4(e + 4)
    }
    if (e + 4 <= e1) { EDGE4(e) e += 4; }
#pragma unroll 1
    for (; e < e1; ++e) {
        int2 p = g_epack[e];
        float w = __int_as_float(p.y);
        float4 v = reinterpret_cast<const float4*>(g_hw + (size_t)p.x * HID)[lane];
        acc.x += w * v.x; acc.y += w * v.y;
        acc.z += w * v.z; acc.w += w * v.w;
    }

    float s = acc.x + acc.y + acc.z + acc.w;
#pragma unroll
    for (int o = 16; o > 0; o >>= 1) s += __shfl_xor_sync(0xffffffffu, s, o);
    float mu = s * (1.f / 128.f);
    float dx = acc.x - mu, dy = acc.y - mu, dz = acc.z - mu, dw = acc.w - mu;
    float q = dx * dx + dy * dy + dz * dz + dw * dw;
#pragma unroll
    for (int o = 16; o > 0; o >>= 1) q += __shfl_xor_sync(0xffffffffu, q, o);
    float rs = rsqrtf(q * (1.f / 128.f) + LN_EPS);

    float4 gm = reinterpret_cast<const float4*>(gamma)[lane];
    float4 bt = reinterpret_cast<const float4*>(beta)[lane];
    float4 r  = reinterpret_cast<const float4*>(g_h + (size_t)node * HID)[lane];
    float4 o;
    o.x = fmaxf(dx * rs * gm.x + bt.x, 0.f) + r.x;
    o.y = fmaxf(dy * rs * gm.y + bt.y, 0.f) + r.y;
    o.z = fmaxf(dz * rs * gm.z + bt.z, 0.f) + r.z;
    o.w = fmaxf(dw * rs * gm.w + bt.w, 0.f) + r.w;
    reinterpret_cast<float4*>(g_h + (size_t)node * HID)[lane] = o;
}

// ---------------- fused pool + MLP (block per graph, atomic-free) ------------
__global__ __launch_bounds__(128) void k_poolmlp(
    const int* __restrict__ batch,
    const float* __restrict__ W1, const float* __restrict__ b1,
    const float* __restrict__ W2, const float* __restrict__ b2,
    float* __restrict__ out)
{
    __shared__ float sp[128];
    __shared__ float part[2];
    int g = blockIdx.x, t = threadIdx.x;

    int lo = 0, hi = N_NODES;
    while (lo < hi) { int m = (lo + hi) >> 1; if (batch[m] < g) lo = m + 1; else hi = m; }
    int start = lo;
    hi = N_NODES;
    while (lo < hi) { int m = (lo + hi) >> 1; if (batch[m] < g + 1) lo = m + 1; else hi = m; }
    int end = lo;

    float acc = 0.f;
    for (int r = start; r < end; ++r) acc += g_h[(size_t)r * HID + t];
    float inv = 1.f / fmaxf((float)(end - start), 1.f);
    sp[t] = acc * inv;
    __syncthreads();

    if (t < 64) {
        float a = b1[t];
#pragma unroll 8
        for (int k = 0; k < 128; ++k) a += sp[k] * W1[t * 128 + k];
        a = fmaxf(a, 0.f);
        float v = a * W2[t];
#pragma unroll
        for (int o = 16; o > 0; o >>= 1) v += __shfl_xor_sync(0xffffffffu, v, o);
        if ((t & 31) == 0) part[t >> 5] = v;
    }
    __syncthreads();
    if (t == 0) out[g] = part[0] + part[1] + b2[0];
}

// ---------------- launch -----------------------------------------------------
extern "C" void kernel_launch(void* const* d_in, const int* in_sizes, int n_in,
                              void* d_out, int out_size) {
    const float* x     = (const float*)d_in[0];
    const int*   ei    = (const int*)  d_in[1];
    const int*   batch = (const int*)  d_in[2];
    const float* W_in  = (const float*)d_in[3];
    const float* b_in  = (const float*)d_in[4];
    const float* Wc    = (const float*)d_in[5];
    const float* bc    = (const float*)d_in[6];
    const float* gamma = (const float*)d_in[7];
    const float* beta  = (const float*)d_in[8];
    const float* W1    = (const float*)d_in[9];
    const float* b1    = (const float*)d_in[10];
    const float* W2    = (const float*)d_in[11];
    const float* b2    = (const float*)d_in[12];
    float* out = (float*)d_out;

    const int* src = ei;
    const int* dst = ei + N_EDGES;

    cudaFuncSetAttribute(k_gemmmma, cudaFuncAttributeMaxDynamicSharedMemorySize,
                         GEMM_SMEM);

    k_wconv<<<4, 128>>>(W_in, Wc);
    k_init<<<(N_NODES + 255) / 256, 256>>>();
    k_hist<<<(N_EDGES + 255) / 256, 256>>>(dst);
    k_scanA<<<SCAN_NB, SCAN_BLK>>>();
    k_scanB<<<1, 256>>>();
    k_scanC<<<SCAN_NB, SCAN_BLK>>>();
    k_fill<<<(N_EDGES + 255) / 256, 256>>>(src, dst);

    int gemm_blocks = (N_NODES + 127) / 128;   // 391
    k_gemmmma<<<gemm_blocks, 256, GEMM_SMEM>>>(x, 0, b_in, N_NODES, 0);

    int gl_blocks = (N_NODES * 32 + 255) / 256;
    for (int l = 0; l < N_LAYERS; ++l) {
        k_gemmmma<<<gemm_blocks, 256, GEMM_SMEM>>>((const float*)0, l + 1,
                                                   (const float*)0, N_NODES, 1);
        k_gatherln<<<gl_blocks, 256>>>(bc + l * HID, gamma + l * HID, beta + l * HID);
    }

    k_poolmlp<<<NUM_GRAPHS, 128>>>(batch, W1, b1, W2, b2, out);
}